// round 2
// baseline (speedup 1.0000x reference)
#include <cuda_runtime.h>
#include <math.h>

// Problem constants
#define BB 8
#define TT 10
#define HH 64
#define WW 64
#define HWP 4096           // H*W
#define FF 64
#define NCH 256            // 4*F
#define M_TOTAL (BB*HWP)   // 32768

// GEMM tiling
#define BM 128
#define BN 128
#define BK 16
#define TM 8
#define TN 8

// Scratch (static device globals; no allocation allowed)
__device__ float g_Wc1[25 * 96 * 256];    // layer1 packed weights [K=2400, 256]
__device__ float g_Wc2[9 * 128 * 256];    // layer2 packed weights [K=1152, 256]
__device__ float g_z[(long)M_TOTAL * NCH];      // per-step gate pre-activations
__device__ float g_h1[(long)BB * TT * HWP * FF]; // relu(h) sequence from layer 1
__device__ float g_h[(long)M_TOTAL * FF];       // current hidden state
__device__ float g_c[(long)M_TOTAL * FF];       // current cell state

// ---------------------------------------------------------------------------
// Pack Wk [kh,kw,Cx,256] and Uk [kh,kw,64,256] into Wc [(pos*Ctot + c), 256]
// where channel c < Cx comes from Wk and c >= Cx from Uk.
// ---------------------------------------------------------------------------
__global__ void pack_weights(const float* __restrict__ Wk,
                             const float* __restrict__ Uk,
                             float* __restrict__ Wc,
                             int KHW, int Cx, int Ctot)
{
    int idx = blockIdx.x * blockDim.x + threadIdx.x;
    int total = KHW * Ctot * NCH;
    if (idx >= total) return;
    int co = idx % NCH;
    int rest = idx / NCH;
    int c = rest % Ctot;
    int pos = rest / Ctot;
    float v;
    if (c < Cx) v = Wk[((long)pos * Cx + c) * NCH + co];
    else        v = Uk[((long)pos * FF + (c - Cx)) * NCH + co];
    Wc[idx] = v;
}

__global__ void zero2(float* __restrict__ a, float* __restrict__ b, int n)
{
    int i = blockIdx.x * blockDim.x + threadIdx.x;
    if (i < n) { a[i] = 0.f; b[i] = 0.f; }
}

// ---------------------------------------------------------------------------
// Implicit-GEMM conv: z[m, n] = sum_k A[m,k] * Wc[k,n]
//   m = (b, y, x) pixel over B*H*W; k = (ky, kx, c) with c over [0, Ctot)
//   c < Cx  -> read x-source at [((b*T + t)*HW + pix)*Cx + c]
//   c >= Cx -> read hprev at [(b*HW + pix)*F + (c-Cx)]
// SAME padding (pad = KH/2), zero fill out of bounds.
// BK=16 always lies inside a single (ky,kx) tap and a single source tensor.
// ---------------------------------------------------------------------------
__global__ void __launch_bounds__(256, 1)
conv_gemm(const float* __restrict__ xsrc, int t, int Cx,
          const float* __restrict__ hprev,
          const float* __restrict__ Wc,
          float* __restrict__ z,
          int KH, int Ctot, int Ktot)
{
    __shared__ float As[BK][BM];
    __shared__ float Bs[BK][BN];

    const int tid = threadIdx.x;
    const int m0 = blockIdx.y * BM;
    const int n0 = blockIdx.x * BN;
    const int pad = KH >> 1;

    const int tr = tid >> 4;   // 0..15
    const int tc = tid & 15;   // 0..15

    float acc[TM][TN];
#pragma unroll
    for (int i = 0; i < TM; i++)
#pragma unroll
        for (int j = 0; j < TN; j++) acc[i][j] = 0.f;

    const int nK = Ktot / BK;
    for (int kt = 0; kt < nK; kt++) {
        const int kk0 = kt * BK;
        const int pos = kk0 / Ctot;
        const int cbase = kk0 - pos * Ctot;
        const int ky = pos / KH;
        const int kx = pos - ky * KH;
        const bool fromX = (cbase < Cx);
        const int c0 = fromX ? cbase : (cbase - Cx);

        // ---- load A tile (im2col gather), 2 x float4 per thread ----
#pragma unroll
        for (int i = 0; i < 2; i++) {
            int e = tid + i * 256;          // 0..511
            int g = e >> 7;                 // k group 0..3 (4 floats each)
            int mloc = e & 127;
            int m = m0 + mloc;
            int b = m >> 12;
            int rem = m & 4095;
            int y = rem >> 6;
            int x = rem & 63;
            int iy = y + ky - pad;
            int ix = x + kx - pad;
            float4 v = make_float4(0.f, 0.f, 0.f, 0.f);
            if ((unsigned)iy < (unsigned)HH && (unsigned)ix < (unsigned)WW) {
                int pix = iy * WW + ix;
                long off;
                if (fromX) off = ((long)(b * TT + t) * HWP + pix) * (long)Cx + c0 + g * 4;
                else       off = ((long)b * HWP + pix) * (long)FF + c0 + g * 4;
                v = *(const float4*)(fromX ? (xsrc + off) : (hprev + off));
            }
            As[g * 4 + 0][mloc] = v.x;
            As[g * 4 + 1][mloc] = v.y;
            As[g * 4 + 2][mloc] = v.z;
            As[g * 4 + 3][mloc] = v.w;
        }

        // ---- load B tile (weights), 2 x float4 per thread, coalesced ----
#pragma unroll
        for (int i = 0; i < 2; i++) {
            int f4 = tid + i * 256;        // 0..511 float4s
            int kloc = f4 >> 5;            // 0..15
            int n4 = f4 & 31;              // 0..31
            float4 v = *(const float4*)(Wc + (long)(kk0 + kloc) * NCH + n0 + n4 * 4);
            *(float4*)&Bs[kloc][n4 * 4] = v;
        }
        __syncthreads();

        // ---- FMA micro-kernel ----
#pragma unroll
        for (int k = 0; k < BK; k++) {
            float ra[TM], rb[TN];
            float4 a0 = *(const float4*)&As[k][tr * TM];
            float4 a1 = *(const float4*)&As[k][tr * TM + 4];
            ra[0] = a0.x; ra[1] = a0.y; ra[2] = a0.z; ra[3] = a0.w;
            ra[4] = a1.x; ra[5] = a1.y; ra[6] = a1.z; ra[7] = a1.w;
            float4 b0 = *(const float4*)&Bs[k][tc * TN];
            float4 b1 = *(const float4*)&Bs[k][tc * TN + 4];
            rb[0] = b0.x; rb[1] = b0.y; rb[2] = b0.z; rb[3] = b0.w;
            rb[4] = b1.x; rb[5] = b1.y; rb[6] = b1.z; rb[7] = b1.w;
#pragma unroll
            for (int i = 0; i < TM; i++)
#pragma unroll
                for (int j = 0; j < TN; j++)
                    acc[i][j] = fmaf(ra[i], rb[j], acc[i][j]);
        }
        __syncthreads();
    }

    // ---- write z ----
#pragma unroll
    for (int i = 0; i < TM; i++) {
        int m = m0 + tr * TM + i;
#pragma unroll
        for (int j = 0; j < TN; j += 4) {
            float4 v = make_float4(acc[i][j], acc[i][j + 1], acc[i][j + 2], acc[i][j + 3]);
            *(float4*)(z + (long)m * NCH + n0 + tc * TN + j) = v;
        }
    }
}

// ---------------------------------------------------------------------------
// LSTM gates: z -> (c_new, h_new), and relu(h_new) into the sequence buffer.
// idx over B*HW*F; m = idx / F, f = idx % F (coalesced on f).
// ---------------------------------------------------------------------------
__device__ __forceinline__ float hsig(float v)
{
    return fminf(fmaxf(0.2f * v + 0.5f, 0.f), 1.f);
}

__global__ void gate_kernel(const float* __restrict__ z,
                            const float* __restrict__ bias,
                            float* __restrict__ c,
                            float* __restrict__ h,
                            float* __restrict__ seqout,
                            int t)
{
    int idx = blockIdx.x * blockDim.x + threadIdx.x;
    if (idx >= M_TOTAL * FF) return;
    int m = idx >> 6;        // / F
    int f = idx & 63;        // % F
    long zb = (long)m * NCH;
    float zi = z[zb + f]          + bias[f];
    float zf = z[zb + FF + f]     + bias[FF + f];
    float zc = z[zb + 2 * FF + f] + bias[2 * FF + f];
    float zo = z[zb + 3 * FF + f] + bias[3 * FF + f];
    float ig = hsig(zi);
    float fg = hsig(zf);
    float og = hsig(zo);
    float cn = fg * c[idx] + ig * tanhf(zc);
    float hn = og * tanhf(cn);
    c[idx] = cn;
    h[idx] = hn;
    int b = m >> 12;
    int pix = m & 4095;
    seqout[((long)(b * TT + t) * HWP + pix) * FF + f] = fmaxf(hn, 0.f);
}

// ---------------------------------------------------------------------------
extern "C" void kernel_launch(void* const* d_in, const int* in_sizes, int n_in,
                              void* d_out, int out_size)
{
    const float* x   = (const float*)d_in[0];
    const float* Wk1 = (const float*)d_in[1];
    const float* Uk1 = (const float*)d_in[2];
    const float* b1  = (const float*)d_in[3];
    const float* Wk2 = (const float*)d_in[4];
    const float* Uk2 = (const float*)d_in[5];
    const float* b2  = (const float*)d_in[6];
    float* out = (float*)d_out;

    float *Wc1, *Wc2, *z, *h1, *h, *c;
    cudaGetSymbolAddress((void**)&Wc1, g_Wc1);
    cudaGetSymbolAddress((void**)&Wc2, g_Wc2);
    cudaGetSymbolAddress((void**)&z,   g_z);
    cudaGetSymbolAddress((void**)&h1,  g_h1);
    cudaGetSymbolAddress((void**)&h,   g_h);
    cudaGetSymbolAddress((void**)&c,   g_c);

    // Pack weights (deterministic, cheap; done every launch)
    {
        int tot1 = 25 * 96 * 256;
        int tot2 = 9 * 128 * 256;
        pack_weights<<<(tot1 + 255) / 256, 256>>>(Wk1, Uk1, Wc1, 25, 32, 96);
        pack_weights<<<(tot2 + 255) / 256, 256>>>(Wk2, Uk2, Wc2, 9, 64, 128);
    }

    const dim3 grid(NCH / BN, M_TOTAL / BM);   // (2, 256)
    const int nstate = M_TOTAL * FF;           // 2,097,152
    const int gateBlocks = (nstate + 255) / 256;

    // ---- Layer 1: 5x5, Cx=32, Ctot=96, K=2400 ----
    zero2<<<gateBlocks, 256>>>(h, c, nstate);
    for (int t = 0; t < TT; t++) {
        conv_gemm<<<grid, 256>>>(x, t, 32, h, Wc1, z, 5, 96, 2400);
        gate_kernel<<<gateBlocks, 256>>>(z, b1, c, h, h1, t);
    }

    // ---- Layer 2: 3x3, Cx=64, Ctot=128, K=1152 ----
    zero2<<<gateBlocks, 256>>>(h, c, nstate);
    for (int t = 0; t < TT; t++) {
        conv_gemm<<<grid, 256>>>(h1, t, 64, h, Wc2, z, 3, 128, 1152);
        gate_kernel<<<gateBlocks, 256>>>(z, b2, c, h, out, t);
    }
}

// round 3
// speedup vs baseline: 1.0001x; 1.0001x over previous
#include <cuda_runtime.h>
#include <math.h>

// Problem constants
#define BB 8
#define TT 10
#define HH 64
#define WW 64
#define HWP 4096           // H*W
#define FF 64
#define NCH 256            // 4*F
#define M_TOTAL (BB*HWP)   // 32768

// GEMM tiling
#define BM 128
#define BN 128
#define BK 16
#define TM 8
#define TN 8

// Scratch (static device globals; no allocation allowed)
__device__ float g_Wc1[25 * 96 * 256];    // layer1 packed weights [K=2400, 256]
__device__ float g_Wc2[9 * 128 * 256];    // layer2 packed weights [K=1152, 256]
__device__ float g_z[(long)M_TOTAL * NCH];      // per-step gate pre-activations
__device__ float g_h1[(long)BB * TT * HWP * FF]; // relu(h) sequence from layer 1
__device__ float g_h[(long)M_TOTAL * FF];       // current hidden state
__device__ float g_c[(long)M_TOTAL * FF];       // current cell state

// ---------------------------------------------------------------------------
// Pack Wk [kh,kw,Cx,256] and Uk [kh,kw,64,256] into Wc [(pos*Ctot + c), 256]
// where channel c < Cx comes from Wk and c >= Cx from Uk.
// ---------------------------------------------------------------------------
__global__ void pack_weights(const float* __restrict__ Wk,
                             const float* __restrict__ Uk,
                             float* __restrict__ Wc,
                             int KHW, int Cx, int Ctot)
{
    int idx = blockIdx.x * blockDim.x + threadIdx.x;
    int total = KHW * Ctot * NCH;
    if (idx >= total) return;
    int co = idx % NCH;
    int rest = idx / NCH;
    int c = rest % Ctot;
    int pos = rest / Ctot;
    float v;
    if (c < Cx) v = Wk[((long)pos * Cx + c) * NCH + co];
    else        v = Uk[((long)pos * FF + (c - Cx)) * NCH + co];
    Wc[idx] = v;
}

__global__ void zero2(float* __restrict__ a, float* __restrict__ b, int n)
{
    int i = blockIdx.x * blockDim.x + threadIdx.x;
    if (i < n) { a[i] = 0.f; b[i] = 0.f; }
}

// ---------------------------------------------------------------------------
// Implicit-GEMM conv: z[m, n] = sum_k A[m,k] * Wc[k,n]
//   m = (b, y, x) pixel over B*H*W; k = (ky, kx, c) with c over [0, Ctot)
//   c < Cx  -> read x-source at [((b*T + t)*HW + pix)*Cx + c]
//   c >= Cx -> read hprev at [(b*HW + pix)*F + (c-Cx)]
// SAME padding (pad = KH/2), zero fill out of bounds.
// BK=16 always lies inside a single (ky,kx) tap and a single source tensor.
// ---------------------------------------------------------------------------
__global__ void __launch_bounds__(256, 1)
conv_gemm(const float* __restrict__ xsrc, int t, int Cx,
          const float* __restrict__ hprev,
          const float* __restrict__ Wc,
          float* __restrict__ z,
          int KH, int Ctot, int Ktot)
{
    __shared__ float As[BK][BM];
    __shared__ float Bs[BK][BN];

    const int tid = threadIdx.x;
    const int m0 = blockIdx.y * BM;
    const int n0 = blockIdx.x * BN;
    const int pad = KH >> 1;

    const int tr = tid >> 4;   // 0..15
    const int tc = tid & 15;   // 0..15

    float acc[TM][TN];
#pragma unroll
    for (int i = 0; i < TM; i++)
#pragma unroll
        for (int j = 0; j < TN; j++) acc[i][j] = 0.f;

    const int nK = Ktot / BK;
    for (int kt = 0; kt < nK; kt++) {
        const int kk0 = kt * BK;
        const int pos = kk0 / Ctot;
        const int cbase = kk0 - pos * Ctot;
        const int ky = pos / KH;
        const int kx = pos - ky * KH;
        const bool fromX = (cbase < Cx);
        const int c0 = fromX ? cbase : (cbase - Cx);

        // ---- load A tile (im2col gather), 2 x float4 per thread ----
#pragma unroll
        for (int i = 0; i < 2; i++) {
            int e = tid + i * 256;          // 0..511
            int g = e >> 7;                 // k group 0..3 (4 floats each)
            int mloc = e & 127;
            int m = m0 + mloc;
            int b = m >> 12;
            int rem = m & 4095;
            int y = rem >> 6;
            int x = rem & 63;
            int iy = y + ky - pad;
            int ix = x + kx - pad;
            float4 v = make_float4(0.f, 0.f, 0.f, 0.f);
            if ((unsigned)iy < (unsigned)HH && (unsigned)ix < (unsigned)WW) {
                int pix = iy * WW + ix;
                long off;
                if (fromX) off = ((long)(b * TT + t) * HWP + pix) * (long)Cx + c0 + g * 4;
                else       off = ((long)b * HWP + pix) * (long)FF + c0 + g * 4;
                v = *(const float4*)(fromX ? (xsrc + off) : (hprev + off));
            }
            As[g * 4 + 0][mloc] = v.x;
            As[g * 4 + 1][mloc] = v.y;
            As[g * 4 + 2][mloc] = v.z;
            As[g * 4 + 3][mloc] = v.w;
        }

        // ---- load B tile (weights), 2 x float4 per thread, coalesced ----
#pragma unroll
        for (int i = 0; i < 2; i++) {
            int f4 = tid + i * 256;        // 0..511 float4s
            int kloc = f4 >> 5;            // 0..15
            int n4 = f4 & 31;              // 0..31
            float4 v = *(const float4*)(Wc + (long)(kk0 + kloc) * NCH + n0 + n4 * 4);
            *(float4*)&Bs[kloc][n4 * 4] = v;
        }
        __syncthreads();

        // ---- FMA micro-kernel ----
#pragma unroll
        for (int k = 0; k < BK; k++) {
            float ra[TM], rb[TN];
            float4 a0 = *(const float4*)&As[k][tr * TM];
            float4 a1 = *(const float4*)&As[k][tr * TM + 4];
            ra[0] = a0.x; ra[1] = a0.y; ra[2] = a0.z; ra[3] = a0.w;
            ra[4] = a1.x; ra[5] = a1.y; ra[6] = a1.z; ra[7] = a1.w;
            float4 b0 = *(const float4*)&Bs[k][tc * TN];
            float4 b1 = *(const float4*)&Bs[k][tc * TN + 4];
            rb[0] = b0.x; rb[1] = b0.y; rb[2] = b0.z; rb[3] = b0.w;
            rb[4] = b1.x; rb[5] = b1.y; rb[6] = b1.z; rb[7] = b1.w;
#pragma unroll
            for (int i = 0; i < TM; i++)
#pragma unroll
                for (int j = 0; j < TN; j++)
                    acc[i][j] = fmaf(ra[i], rb[j], acc[i][j]);
        }
        __syncthreads();
    }

    // ---- write z ----
#pragma unroll
    for (int i = 0; i < TM; i++) {
        int m = m0 + tr * TM + i;
#pragma unroll
        for (int j = 0; j < TN; j += 4) {
            float4 v = make_float4(acc[i][j], acc[i][j + 1], acc[i][j + 2], acc[i][j + 3]);
            *(float4*)(z + (long)m * NCH + n0 + tc * TN + j) = v;
        }
    }
}

// ---------------------------------------------------------------------------
// LSTM gates: z -> (c_new, h_new), and relu(h_new) into the sequence buffer.
// idx over B*HW*F; m = idx / F, f = idx % F (coalesced on f).
// ---------------------------------------------------------------------------
__device__ __forceinline__ float hsig(float v)
{
    return fminf(fmaxf(0.2f * v + 0.5f, 0.f), 1.f);
}

__global__ void gate_kernel(const float* __restrict__ z,
                            const float* __restrict__ bias,
                            float* __restrict__ c,
                            float* __restrict__ h,
                            float* __restrict__ seqout,
                            int t)
{
    int idx = blockIdx.x * blockDim.x + threadIdx.x;
    if (idx >= M_TOTAL * FF) return;
    int m = idx >> 6;        // / F
    int f = idx & 63;        // % F
    long zb = (long)m * NCH;
    float zi = z[zb + f]          + bias[f];
    float zf = z[zb + FF + f]     + bias[FF + f];
    float zc = z[zb + 2 * FF + f] + bias[2 * FF + f];
    float zo = z[zb + 3 * FF + f] + bias[3 * FF + f];
    float ig = hsig(zi);
    float fg = hsig(zf);
    float og = hsig(zo);
    float cn = fg * c[idx] + ig * tanhf(zc);
    float hn = og * tanhf(cn);
    c[idx] = cn;
    h[idx] = hn;
    int b = m >> 12;
    int pix = m & 4095;
    seqout[((long)(b * TT + t) * HWP + pix) * FF + f] = fmaxf(hn, 0.f);
}

// ---------------------------------------------------------------------------
extern "C" void kernel_launch(void* const* d_in, const int* in_sizes, int n_in,
                              void* d_out, int out_size)
{
    const float* x   = (const float*)d_in[0];
    const float* Wk1 = (const float*)d_in[1];
    const float* Uk1 = (const float*)d_in[2];
    const float* b1  = (const float*)d_in[3];
    const float* Wk2 = (const float*)d_in[4];
    const float* Uk2 = (const float*)d_in[5];
    const float* b2  = (const float*)d_in[6];
    float* out = (float*)d_out;

    float *Wc1, *Wc2, *z, *h1, *h, *c;
    cudaGetSymbolAddress((void**)&Wc1, g_Wc1);
    cudaGetSymbolAddress((void**)&Wc2, g_Wc2);
    cudaGetSymbolAddress((void**)&z,   g_z);
    cudaGetSymbolAddress((void**)&h1,  g_h1);
    cudaGetSymbolAddress((void**)&h,   g_h);
    cudaGetSymbolAddress((void**)&c,   g_c);

    // Pack weights (deterministic, cheap; done every launch)
    {
        int tot1 = 25 * 96 * 256;
        int tot2 = 9 * 128 * 256;
        pack_weights<<<(tot1 + 255) / 256, 256>>>(Wk1, Uk1, Wc1, 25, 32, 96);
        pack_weights<<<(tot2 + 255) / 256, 256>>>(Wk2, Uk2, Wc2, 9, 64, 128);
    }

    const dim3 grid(NCH / BN, M_TOTAL / BM);   // (2, 256)
    const int nstate = M_TOTAL * FF;           // 2,097,152
    const int gateBlocks = (nstate + 255) / 256;

    // ---- Layer 1: 5x5, Cx=32, Ctot=96, K=2400 ----
    zero2<<<gateBlocks, 256>>>(h, c, nstate);
    for (int t = 0; t < TT; t++) {
        conv_gemm<<<grid, 256>>>(x, t, 32, h, Wc1, z, 5, 96, 2400);
        gate_kernel<<<gateBlocks, 256>>>(z, b1, c, h, h1, t);
    }

    // ---- Layer 2: 3x3, Cx=64, Ctot=128, K=1152 ----
    zero2<<<gateBlocks, 256>>>(h, c, nstate);
    for (int t = 0; t < TT; t++) {
        conv_gemm<<<grid, 256>>>(h1, t, 64, h, Wc2, z, 3, 128, 1152);
        gate_kernel<<<gateBlocks, 256>>>(z, b2, c, h, out, t);
    }
}

// round 4
// speedup vs baseline: 1.1753x; 1.1752x over previous
#include <cuda_runtime.h>
#include <math.h>

// Problem constants
#define BB 8
#define TT 10
#define HH 64
#define WW 64
#define HWP 4096           // H*W
#define FF 64
#define NCH 256            // 4*F
#define M_TOTAL (BB*HWP)   // 32768

// GEMM tiling
#define BM 128
#define BN 128
#define BK 16
#define TM 8
#define TN 8

typedef unsigned long long u64;

// Packed fp32x2 FMA (sm_103a FFMA2) — 2 FMAs per issue slot
#define FMA_F32X2(d, a, b) \
    asm("fma.rn.f32x2 %0, %1, %2, %0;" : "+l"(d) : "l"(a), "l"(b))

// Duplicate one fp32 into both lanes of a packed pair
#define PACK_DUP(d, s) \
    asm("mov.b64 %0, {%1, %1};" : "=l"(d) : "r"(__float_as_uint(s)))

// Scratch (static device globals; no allocation allowed)
__device__ float g_Wc1[25 * 96 * 256];    // layer1 packed weights [K=2400, 256]
__device__ float g_Wc2[9 * 128 * 256];    // layer2 packed weights [K=1152, 256]
__device__ float g_z[(long)M_TOTAL * NCH];       // per-step gate pre-activations
__device__ float g_h1[(long)BB * TT * HWP * FF]; // relu(h) sequence from layer 1
__device__ float g_h[(long)M_TOTAL * FF];        // current hidden state
__device__ float g_c[(long)M_TOTAL * FF];        // current cell state

// ---------------------------------------------------------------------------
// Pack Wk [kh,kw,Cx,256] and Uk [kh,kw,64,256] into Wc [(pos*Ctot + c), 256]
// ---------------------------------------------------------------------------
__global__ void pack_weights(const float* __restrict__ Wk,
                             const float* __restrict__ Uk,
                             float* __restrict__ Wc,
                             int KHW, int Cx, int Ctot)
{
    int idx = blockIdx.x * blockDim.x + threadIdx.x;
    int total = KHW * Ctot * NCH;
    if (idx >= total) return;
    int co = idx % NCH;
    int rest = idx / NCH;
    int c = rest % Ctot;
    int pos = rest / Ctot;
    float v;
    if (c < Cx) v = Wk[((long)pos * Cx + c) * NCH + co];
    else        v = Uk[((long)pos * FF + (c - Cx)) * NCH + co];
    Wc[idx] = v;
}

__global__ void zero2(float* __restrict__ a, float* __restrict__ b, int n)
{
    int i = blockIdx.x * blockDim.x + threadIdx.x;
    if (i < n) { a[i] = 0.f; b[i] = 0.f; }
}

// ---------------------------------------------------------------------------
// Implicit-GEMM conv, double-buffered + packed f32x2 math.
//   z[m,n] = sum_k A[m,k] * Wc[k,n]
//   m = (b,y,x); k = (ky,kx,c); c<Cx from x-source, else from hprev.
// BK divides Ctot, so each K-slice has fixed (ky,kx) and a single source.
// ---------------------------------------------------------------------------
template<int KH, int Cx, int Ctot, int Ktot>
__global__ void __launch_bounds__(256, 1)
conv_gemm(const float* __restrict__ xsrc, int t,
          const float* __restrict__ hprev,
          const float* __restrict__ Wc,
          float* __restrict__ z)
{
    __shared__ float As[2][BK][BM];
    __shared__ float Bs[2][BK][BN];

    const int tid = threadIdx.x;
    const int m0 = blockIdx.y * BM;
    const int n0 = blockIdx.x * BN;
    constexpr int pad = KH >> 1;
    constexpr int nK = Ktot / BK;

    const int tr = tid >> 4;   // 0..15
    const int tc = tid & 15;   // 0..15

    // per-thread load geometry (invariant across K-slices)
    int gA[2], yA[2], xA[2], mlocA[2];
    long baseX[2], baseH[2];
#pragma unroll
    for (int i = 0; i < 2; i++) {
        int e = tid + i * 256;
        gA[i] = e >> 7;                 // k-group 0..3
        int mloc = e & 127; mlocA[i] = mloc;
        int m = m0 + mloc;
        int b = m >> 12;
        int rem = m & 4095;
        yA[i] = rem >> 6;
        xA[i] = rem & 63;
        baseX[i] = (long)(b * TT + t) * HWP * Cx + gA[i] * 4;
        baseH[i] = (long)b * HWP * FF + gA[i] * 4;
    }
    const int kloc[2] = { tid >> 5, (tid + 256) >> 5 };
    const int n4[2]   = { tid & 31, (tid + 256) & 31 };

    u64 acc[TM][TN / 2];
#pragma unroll
    for (int i = 0; i < TM; i++)
#pragma unroll
        for (int j = 0; j < TN / 2; j++) acc[i][j] = 0ull;

    float4 av[2], bv[2];

    auto load_tile = [&](int kk0) {
        int pos   = kk0 / Ctot;          // compile-time-const divisor
        int cbase = kk0 - pos * Ctot;
        int ky = pos / KH;
        int kx = pos - ky * KH;
        bool fromX = (cbase < Cx);
        int c0 = fromX ? cbase : (cbase - Cx);
#pragma unroll
        for (int i = 0; i < 2; i++) {
            int iy = yA[i] + ky - pad;
            int ix = xA[i] + kx - pad;
            av[i] = make_float4(0.f, 0.f, 0.f, 0.f);
            if ((unsigned)iy < (unsigned)HH && (unsigned)ix < (unsigned)WW) {
                int pix = iy * WW + ix;
                const float* p = fromX
                    ? (xsrc  + baseX[i] + (long)pix * Cx + c0)
                    : (hprev + baseH[i] + (long)pix * FF + c0);
                av[i] = *(const float4*)p;
            }
        }
#pragma unroll
        for (int i = 0; i < 2; i++)
            bv[i] = *(const float4*)(Wc + (long)(kk0 + kloc[i]) * NCH + n0 + n4[i] * 4);
    };

    auto store_tile = [&](int buf) {
#pragma unroll
        for (int i = 0; i < 2; i++) {
            As[buf][gA[i] * 4 + 0][mlocA[i]] = av[i].x;
            As[buf][gA[i] * 4 + 1][mlocA[i]] = av[i].y;
            As[buf][gA[i] * 4 + 2][mlocA[i]] = av[i].z;
            As[buf][gA[i] * 4 + 3][mlocA[i]] = av[i].w;
        }
#pragma unroll
        for (int i = 0; i < 2; i++)
            *(float4*)&Bs[buf][kloc[i]][n4[i] * 4] = bv[i];
    };

    // prologue: tile 0
    load_tile(0);
    store_tile(0);
    __syncthreads();

    for (int kt = 0; kt < nK; kt++) {
        const int cur = kt & 1;
        const bool more = (kt + 1 < nK);
        if (more) load_tile((kt + 1) * BK);   // global loads in flight during compute

        // ---- packed-FMA micro-kernel ----
#pragma unroll
        for (int k = 0; k < BK; k++) {
            float4 a0 = *(const float4*)&As[cur][k][tr * TM];
            float4 a1 = *(const float4*)&As[cur][k][tr * TM + 4];
            u64 ap[TM];
            PACK_DUP(ap[0], a0.x); PACK_DUP(ap[1], a0.y);
            PACK_DUP(ap[2], a0.z); PACK_DUP(ap[3], a0.w);
            PACK_DUP(ap[4], a1.x); PACK_DUP(ap[5], a1.y);
            PACK_DUP(ap[6], a1.z); PACK_DUP(ap[7], a1.w);
            const u64* bp = (const u64*)&Bs[cur][k][tc * TN];
            u64 b0 = bp[0], b1 = bp[1], b2 = bp[2], b3 = bp[3];
#pragma unroll
            for (int i = 0; i < TM; i++) {
                FMA_F32X2(acc[i][0], ap[i], b0);
                FMA_F32X2(acc[i][1], ap[i], b1);
                FMA_F32X2(acc[i][2], ap[i], b2);
                FMA_F32X2(acc[i][3], ap[i], b3);
            }
        }

        if (more) store_tile(cur ^ 1);
        __syncthreads();
    }

    // ---- write z (packed pairs: low lane = even column) ----
#pragma unroll
    for (int i = 0; i < TM; i++) {
        long row = (long)(m0 + tr * TM + i) * NCH + n0 + tc * TN;
#pragma unroll
        for (int j = 0; j < TN / 2; j++)
            *(u64*)(z + row + j * 2) = acc[i][j];
    }
}

// ---------------------------------------------------------------------------
// LSTM gates: z -> (c_new, h_new), and relu(h_new) into the sequence buffer.
// ---------------------------------------------------------------------------
__device__ __forceinline__ float hsig(float v)
{
    return fminf(fmaxf(0.2f * v + 0.5f, 0.f), 1.f);
}

__global__ void gate_kernel(const float* __restrict__ z,
                            const float* __restrict__ bias,
                            float* __restrict__ c,
                            float* __restrict__ h,
                            float* __restrict__ seqout,
                            int t)
{
    int idx = blockIdx.x * blockDim.x + threadIdx.x;
    if (idx >= M_TOTAL * FF) return;
    int m = idx >> 6;        // / F
    int f = idx & 63;        // % F
    long zb = (long)m * NCH;
    float zi = z[zb + f]          + bias[f];
    float zf = z[zb + FF + f]     + bias[FF + f];
    float zc = z[zb + 2 * FF + f] + bias[2 * FF + f];
    float zo = z[zb + 3 * FF + f] + bias[3 * FF + f];
    float ig = hsig(zi);
    float fg = hsig(zf);
    float og = hsig(zo);
    float cn = fg * c[idx] + ig * tanhf(zc);
    float hn = og * tanhf(cn);
    c[idx] = cn;
    h[idx] = hn;
    int b = m >> 12;
    int pix = m & 4095;
    seqout[((long)(b * TT + t) * HWP + pix) * FF + f] = fmaxf(hn, 0.f);
}

// ---------------------------------------------------------------------------
extern "C" void kernel_launch(void* const* d_in, const int* in_sizes, int n_in,
                              void* d_out, int out_size)
{
    const float* x   = (const float*)d_in[0];
    const float* Wk1 = (const float*)d_in[1];
    const float* Uk1 = (const float*)d_in[2];
    const float* b1  = (const float*)d_in[3];
    const float* Wk2 = (const float*)d_in[4];
    const float* Uk2 = (const float*)d_in[5];
    const float* b2  = (const float*)d_in[6];
    float* out = (float*)d_out;

    float *Wc1, *Wc2, *z, *h1, *h, *c;
    cudaGetSymbolAddress((void**)&Wc1, g_Wc1);
    cudaGetSymbolAddress((void**)&Wc2, g_Wc2);
    cudaGetSymbolAddress((void**)&z,   g_z);
    cudaGetSymbolAddress((void**)&h1,  g_h1);
    cudaGetSymbolAddress((void**)&h,   g_h);
    cudaGetSymbolAddress((void**)&c,   g_c);

    // Pack weights (deterministic, cheap; done every launch)
    {
        int tot1 = 25 * 96 * 256;
        int tot2 = 9 * 128 * 256;
        pack_weights<<<(tot1 + 255) / 256, 256>>>(Wk1, Uk1, Wc1, 25, 32, 96);
        pack_weights<<<(tot2 + 255) / 256, 256>>>(Wk2, Uk2, Wc2, 9, 64, 128);
    }

    const dim3 grid(NCH / BN, M_TOTAL / BM);   // (2, 256)
    const int nstate = M_TOTAL * FF;           // 2,097,152
    const int gateBlocks = (nstate + 255) / 256;

    // ---- Layer 1: 5x5, Cx=32, Ctot=96, K=2400 ----
    zero2<<<gateBlocks, 256>>>(h, c, nstate);
    for (int t = 0; t < TT; t++) {
        conv_gemm<5, 32, 96, 2400><<<grid, 256>>>(x, t, h, Wc1, z);
        gate_kernel<<<gateBlocks, 256>>>(z, b1, c, h, h1, t);
    }

    // ---- Layer 2: 3x3, Cx=64, Ctot=128, K=1152 ----
    zero2<<<gateBlocks, 256>>>(h, c, nstate);
    for (int t = 0; t < TT; t++) {
        conv_gemm<3, 64, 128, 1152><<<grid, 256>>>(h1, t, h, Wc2, z);
        gate_kernel<<<gateBlocks, 256>>>(z, b2, c, h, out, t);
    }
}

// round 5
// speedup vs baseline: 1.4070x; 1.1972x over previous
#include <cuda_runtime.h>
#include <math.h>

// Problem constants
#define BB 8
#define TT 10
#define HH 64
#define WW 64
#define HWP 4096           // H*W
#define FF 64
#define NCH 256            // 4*F
#define M_TOTAL (BB*HWP)   // 32768

// Planar halo layout: 2-pixel border on each side
#define HR 68              // padded row length
#define PLANE (HR*HR)      // 4624 floats per channel plane

// GEMM tiling
#define BM 128
#define BN 128
#define BK 16
#define TM 8
#define TN 8

typedef unsigned long long u64;

// Packed fp32x2 FMA (sm_103a FFMA2) — 2 FMAs per issue slot
#define FMA_F32X2(d, a, b) \
    asm("fma.rn.f32x2 %0, %1, %2, %0;" : "+l"(d) : "l"(a), "l"(b))

#define PACK_DUP(d, s) \
    asm("mov.b64 %0, {%1, %1};" : "=l"(d) : "r"(__float_as_uint(s)))

// Scratch (static device globals; no allocation allowed)
__device__ float g_Wc1[25 * 96 * 256];             // layer1 packed weights [2400,256]
__device__ float g_Wc2[9 * 128 * 256];             // layer2 packed weights [1152,256]
__device__ float g_z[(long)M_TOTAL * NCH];         // gate pre-activations [m][n]
__device__ float g_xp[(long)BB * TT * 32 * PLANE]; // x transposed planar+halo
__device__ float g_h1[(long)BB * TT * FF * PLANE]; // relu(h) seq layer1, planar+halo
__device__ float g_h[(long)BB * FF * PLANE];       // hidden state, planar+halo
__device__ float g_c[(long)BB * FF * HWP];         // cell state, planar (no halo)

// ---------------------------------------------------------------------------
__global__ void zerok(float4* __restrict__ p, long n4)
{
    long stride = (long)gridDim.x * blockDim.x;
    for (long i = blockIdx.x * (long)blockDim.x + threadIdx.x; i < n4; i += stride)
        p[i] = make_float4(0.f, 0.f, 0.f, 0.f);
}

// ---------------------------------------------------------------------------
// Pack Wk [kh,kw,Cx,256] and Uk [kh,kw,64,256] into Wc [(pos*Ctot + c), 256]
// ---------------------------------------------------------------------------
__global__ void pack_weights(const float* __restrict__ Wk,
                             const float* __restrict__ Uk,
                             float* __restrict__ Wc,
                             int KHW, int Cx, int Ctot)
{
    int idx = blockIdx.x * blockDim.x + threadIdx.x;
    int total = KHW * Ctot * NCH;
    if (idx >= total) return;
    int co = idx % NCH;
    int rest = idx / NCH;
    int c = rest % Ctot;
    int pos = rest / Ctot;
    float v;
    if (c < Cx) v = Wk[((long)pos * Cx + c) * NCH + co];
    else        v = Uk[((long)pos * FF + (c - Cx)) * NCH + co];
    Wc[idx] = v;
}

// ---------------------------------------------------------------------------
// Transpose x [b,t,pix,32] (NHWC) -> xp [b,t,32,PLANE] planar+halo (one-time)
// ---------------------------------------------------------------------------
__global__ void transpose_x(const float* __restrict__ x, float* __restrict__ xp)
{
    long idx = blockIdx.x * (long)blockDim.x + threadIdx.x;
    if (idx >= (long)BB * TT * 32 * HWP) return;
    int pix = idx & 4095;
    long rest = idx >> 12;
    int ch = (int)(rest & 31);
    long bt = rest >> 5;
    float v = x[(bt * HWP + pix) * 32 + ch];
    int y = pix >> 6, xx = pix & 63;
    xp[(bt * 32 + ch) * PLANE + (y + 2) * HR + xx + 2] = v;
}

// ---------------------------------------------------------------------------
// Implicit-GEMM conv, planar+halo A source, double-buffered, packed f32x2.
//   z[m,n] = sum_k A[m,k] * Wc[k,n]
// A reads: channel plane (from xsrc if c<Cx else hprev), pixel shifted by tap,
// halo pre-zeroed -> NO boundary predication, fully coalesced scalar loads.
// ---------------------------------------------------------------------------
template<int KH, int Cx, int Ctot, int Ktot>
__global__ void __launch_bounds__(256, 2)
conv_gemm(const float* __restrict__ xsrc, int t,
          const float* __restrict__ hprev,
          const float* __restrict__ Wc,
          float* __restrict__ z)
{
    __shared__ float As[2][BK][BM];
    __shared__ float Bs[2][BK][BN];

    const int tid = threadIdx.x;
    const int m0 = blockIdx.y * BM;
    const int n0 = blockIdx.x * BN;
    constexpr int pad = KH >> 1;
    constexpr int HOFF = 2 - pad;       // halo alignment offset
    constexpr int nK = Ktot / BK;

    const int tr = tid >> 4;   // 0..15
    const int tc = tid & 15;   // 0..15

    const int b = m0 >> 12;            // batch (uniform per block)
    const int y0 = (m0 & 4095) >> 6;   // 2 rows per block (BM=128)

    // A-load geometry: element e = r*256 + tid -> k = e>>7, p = e&127
    const int khalf = tid >> 7;        // 0/1
    const int p = tid & 127;
    const int prow = (y0 + (p >> 6)) * HR + (p & 63);  // unshifted position

    // B-load geometry
    const int kloc[2] = { tid >> 5, (tid + 256) >> 5 };
    const int n4[2]   = { tid & 31, (tid + 256) & 31 };

    u64 acc[TM][TN / 2];
#pragma unroll
    for (int i = 0; i < TM; i++)
#pragma unroll
        for (int j = 0; j < TN / 2; j++) acc[i][j] = 0ull;

    float av[8];
    float4 bv[2];

    auto load_tile = [&](int kk0) {
        int pos   = kk0 / Ctot;
        int cbase = kk0 - pos * Ctot;
        int ky = pos / KH;
        int kx = pos - ky * KH;
        bool fromX = (cbase < Cx);
        const float* base;
        if (fromX) base = xsrc  + ((long)(b * TT + t) * Cx + cbase) * PLANE;
        else       base = hprev + ((long)b * FF + (cbase - Cx)) * PLANE;
        const int shift = (ky + HOFF) * HR + kx + HOFF;
        const float* src = base + (long)khalf * PLANE + prow + shift;
#pragma unroll
        for (int r = 0; r < 8; r++)
            av[r] = src[(long)r * 2 * PLANE];
#pragma unroll
        for (int i = 0; i < 2; i++)
            bv[i] = *(const float4*)(Wc + (long)(kk0 + kloc[i]) * NCH + n0 + n4[i] * 4);
    };

    auto store_tile = [&](int buf) {
#pragma unroll
        for (int r = 0; r < 8; r++)
            As[buf][r * 2 + khalf][p] = av[r];
#pragma unroll
        for (int i = 0; i < 2; i++)
            *(float4*)&Bs[buf][kloc[i]][n4[i] * 4] = bv[i];
    };

    load_tile(0);
    store_tile(0);
    __syncthreads();

    for (int kt = 0; kt < nK; kt++) {
        const int cur = kt & 1;
        const bool more = (kt + 1 < nK);
        if (more) load_tile((kt + 1) * BK);

#pragma unroll
        for (int k = 0; k < BK; k++) {
            float4 a0 = *(const float4*)&As[cur][k][tr * TM];
            float4 a1 = *(const float4*)&As[cur][k][tr * TM + 4];
            u64 ap[TM];
            PACK_DUP(ap[0], a0.x); PACK_DUP(ap[1], a0.y);
            PACK_DUP(ap[2], a0.z); PACK_DUP(ap[3], a0.w);
            PACK_DUP(ap[4], a1.x); PACK_DUP(ap[5], a1.y);
            PACK_DUP(ap[6], a1.z); PACK_DUP(ap[7], a1.w);
            const u64* bp = (const u64*)&Bs[cur][k][tc * TN];
            u64 b0 = bp[0], b1 = bp[1], b2 = bp[2], b3 = bp[3];
#pragma unroll
            for (int i = 0; i < TM; i++) {
                FMA_F32X2(acc[i][0], ap[i], b0);
                FMA_F32X2(acc[i][1], ap[i], b1);
                FMA_F32X2(acc[i][2], ap[i], b2);
                FMA_F32X2(acc[i][3], ap[i], b3);
            }
        }

        if (more) store_tile(cur ^ 1);
        __syncthreads();
    }

#pragma unroll
    for (int i = 0; i < TM; i++) {
        long row = (long)(m0 + tr * TM + i) * NCH + n0 + tc * TN;
#pragma unroll
        for (int j = 0; j < TN / 2; j++)
            *(u64*)(z + row + j * 2) = acc[i][j];
    }
}

// ---------------------------------------------------------------------------
__device__ __forceinline__ float hsig(float v)
{
    return fminf(fmaxf(0.2f * v + 0.5f, 0.f), 1.f);
}

// Layer-1 gates: z[m][n] -> c, h (planar+halo), relu(h) -> h1 seq (planar+halo)
// Block = 32 consecutive pixels (one batch, one row segment), 256 threads.
__global__ void __launch_bounds__(256, 2)
gate1(const float* __restrict__ z, const float* __restrict__ bias,
      float* __restrict__ c, float* __restrict__ h,
      float* __restrict__ h1seq, int t)
{
    __shared__ float zs[256 * 33];
    const int tid = threadIdx.x;
    const int m0 = blockIdx.x * 32;
    const int b = m0 >> 12;
    const int pix0 = m0 & 4095;

    // phase 1: transpose z tile into smem (+bias)
    float bvv = bias[tid];
    const float* zrow = z + (long)m0 * NCH + tid;
#pragma unroll 8
    for (int r = 0; r < 32; r++)
        zs[tid * 33 + r] = zrow[(long)r * NCH] + bvv;
    __syncthreads();

    // phase 2: compute, coalesced planar writes
    const int lane = tid & 31;
    const int fq = tid >> 5;
    const int pix = pix0 + lane;
    const int y = pix >> 6, xx = pix & 63;
    const long hb = (long)b * FF * PLANE;
    const long sb = (long)(b * TT + t) * FF * PLANE;
    const int hoffpix = (y + 2) * HR + xx + 2;
#pragma unroll
    for (int ff = 0; ff < 8; ff++) {
        int f = fq * 8 + ff;
        float zi = zs[f * 33 + lane];
        float zf = zs[(64 + f) * 33 + lane];
        float zc = zs[(128 + f) * 33 + lane];
        float zo = zs[(192 + f) * 33 + lane];
        long cidx = ((long)b * FF + f) * HWP + pix;
        float cn = hsig(zf) * c[cidx] + hsig(zi) * tanhf(zc);
        float hn = hsig(zo) * tanhf(cn);
        c[cidx] = cn;
        long ho = (long)f * PLANE + hoffpix;
        h[hb + ho] = hn;
        h1seq[sb + ho] = fmaxf(hn, 0.f);
    }
}

// Layer-2 gates: also emit NHWC output via a second smem transpose.
__global__ void __launch_bounds__(256, 2)
gate2(const float* __restrict__ z, const float* __restrict__ bias,
      float* __restrict__ c, float* __restrict__ h,
      float* __restrict__ out, int t)
{
    __shared__ float zs[256 * 33];
    __shared__ float hs[64 * 33];
    const int tid = threadIdx.x;
    const int m0 = blockIdx.x * 32;
    const int b = m0 >> 12;
    const int pix0 = m0 & 4095;

    float bvv = bias[tid];
    const float* zrow = z + (long)m0 * NCH + tid;
#pragma unroll 8
    for (int r = 0; r < 32; r++)
        zs[tid * 33 + r] = zrow[(long)r * NCH] + bvv;
    __syncthreads();

    const int lane = tid & 31;
    const int fq = tid >> 5;
    const int pix = pix0 + lane;
    const int y = pix >> 6, xx = pix & 63;
    const long hb = (long)b * FF * PLANE;
    const int hoffpix = (y + 2) * HR + xx + 2;
#pragma unroll
    for (int ff = 0; ff < 8; ff++) {
        int f = fq * 8 + ff;
        float zi = zs[f * 33 + lane];
        float zf = zs[(64 + f) * 33 + lane];
        float zc = zs[(128 + f) * 33 + lane];
        float zo = zs[(192 + f) * 33 + lane];
        long cidx = ((long)b * FF + f) * HWP + pix;
        float cn = hsig(zf) * c[cidx] + hsig(zi) * tanhf(zc);
        float hn = hsig(zo) * tanhf(cn);
        c[cidx] = cn;
        h[hb + (long)f * PLANE + hoffpix] = hn;
        hs[f * 33 + lane] = fmaxf(hn, 0.f);
    }
    __syncthreads();

    // phase 3: NHWC output, coalesced
    float* ob = out + ((long)(b * TT + t) * HWP + pix0) * FF;
#pragma unroll
    for (int r = 0; r < 8; r++) {
        int e = r * 256 + tid;
        int f = e & 63;
        int mo = e >> 6;
        ob[(long)mo * FF + f] = hs[f * 33 + mo];
    }
}

// ---------------------------------------------------------------------------
extern "C" void kernel_launch(void* const* d_in, const int* in_sizes, int n_in,
                              void* d_out, int out_size)
{
    const float* x   = (const float*)d_in[0];
    const float* Wk1 = (const float*)d_in[1];
    const float* Uk1 = (const float*)d_in[2];
    const float* b1  = (const float*)d_in[3];
    const float* Wk2 = (const float*)d_in[4];
    const float* Uk2 = (const float*)d_in[5];
    const float* b2  = (const float*)d_in[6];
    float* out = (float*)d_out;

    float *Wc1, *Wc2, *z, *xp, *h1, *h, *c;
    cudaGetSymbolAddress((void**)&Wc1, g_Wc1);
    cudaGetSymbolAddress((void**)&Wc2, g_Wc2);
    cudaGetSymbolAddress((void**)&z,   g_z);
    cudaGetSymbolAddress((void**)&xp,  g_xp);
    cudaGetSymbolAddress((void**)&h1,  g_h1);
    cudaGetSymbolAddress((void**)&h,   g_h);
    cudaGetSymbolAddress((void**)&c,   g_c);

    // Zero planar buffers (halos must be 0; interiors rewritten each launch)
    zerok<<<1024, 256>>>((float4*)xp, (long)BB * TT * 32 * PLANE / 4);
    zerok<<<1024, 256>>>((float4*)h1, (long)BB * TT * FF * PLANE / 4);

    // Pack weights + transpose x
    {
        int tot1 = 25 * 96 * 256;
        int tot2 = 9 * 128 * 256;
        pack_weights<<<(tot1 + 255) / 256, 256>>>(Wk1, Uk1, Wc1, 25, 32, 96);
        pack_weights<<<(tot2 + 255) / 256, 256>>>(Wk2, Uk2, Wc2, 9, 64, 128);
        long totx = (long)BB * TT * 32 * HWP;
        transpose_x<<<(int)((totx + 255) / 256), 256>>>(x, xp);
    }

    const dim3 grid(NCH / BN, M_TOTAL / BM);   // (2, 256)
    const int gateBlocks = M_TOTAL / 32;       // 1024

    // ---- Layer 1: 5x5, Cx=32, Ctot=96, K=2400 ----
    zerok<<<1024, 256>>>((float4*)h, (long)BB * FF * PLANE / 4);
    zerok<<<1024, 256>>>((float4*)c, (long)BB * FF * HWP / 4);
    for (int t = 0; t < TT; t++) {
        conv_gemm<5, 32, 96, 2400><<<grid, 256>>>(xp, t, h, Wc1, z);
        gate1<<<gateBlocks, 256>>>(z, b1, c, h, h1, t);
    }

    // ---- Layer 2: 3x3, Cx=64, Ctot=128, K=1152 ----
    zerok<<<1024, 256>>>((float4*)h, (long)BB * FF * PLANE / 4);
    zerok<<<1024, 256>>>((float4*)c, (long)BB * FF * HWP / 4);
    for (int t = 0; t < TT; t++) {
        conv_gemm<3, 64, 128, 1152><<<grid, 256>>>(h1, t, h, Wc2, z);
        gate2<<<gateBlocks, 256>>>(z, b2, c, h, out, t);
    }
}

// round 7
// speedup vs baseline: 3.2817x; 2.3324x over previous
#include <cuda_runtime.h>
#include <cuda_bf16.h>
#include <math.h>

// Problem constants
#define BB 8
#define TT 10
#define HH 64
#define WW 64
#define HWP 4096           // H*W
#define FF 64
#define NCH 256            // 4*F
#define M_TOTAL (BB*HWP)   // 32768

// Planar halo layout: 2-pixel border on each side
#define HR 68
#define PLANE (HR*HR)      // 4624 floats per channel plane

// Per-layer chunk counts (original K / 16)
#define NCH1 150           // 2400/16
#define NCH2 72            // 1152/16

#define SM_TOTAL 65536     // A[2][16K] + B[2][16K]

typedef unsigned long long u64;

// Scratch (static device globals; no allocation allowed)
__device__ float g_z[(long)M_TOTAL * NCH];          // gate pre-activations [m][n]
__device__ float g_xp[(long)BB * TT * 32 * PLANE];  // x transposed planar+halo
__device__ float g_h1[(long)BB * TT * FF * PLANE];  // relu(h) seq layer1, planar+halo
__device__ float g_h[(long)BB * FF * PLANE];        // hidden state, planar+halo
__device__ float g_c[(long)BB * FF * HWP];          // cell state, planar
__device__ __nv_bfloat16 g_B1[(long)2 * NCH1 * 8192]; // layer1 prepacked B tiles
__device__ __nv_bfloat16 g_B2[(long)2 * NCH2 * 8192]; // layer2 prepacked B tiles

// ---------------------------------------------------------------------------
// Helpers (sm_80-baseline PTX only — harness targets family-generic sm_103)
// ---------------------------------------------------------------------------
__device__ __forceinline__ unsigned smem_u32(const void* p) {
    unsigned r;
    asm("{ .reg .u64 t; cvta.to.shared.u64 t, %1; cvt.u32.u64 %0, t; }"
        : "=r"(r) : "l"(p));
    return r;
}
__device__ __forceinline__ unsigned pack_bf16x2(float hi, float lo) {
    unsigned r;
    asm("cvt.rn.bf16x2.f32 %0, %1, %2;" : "=r"(r) : "f"(hi), "f"(lo));
    return r;
}
__device__ __forceinline__ void ldsm4(unsigned* r, unsigned addr) {
    asm volatile("ldmatrix.sync.aligned.m8n8.x4.shared.b16 {%0,%1,%2,%3}, [%4];"
                 : "=r"(r[0]), "=r"(r[1]), "=r"(r[2]), "=r"(r[3]) : "r"(addr));
}
__device__ __forceinline__ void mma_bf16(float* c, const unsigned* a,
                                         unsigned b0, unsigned b1) {
    asm volatile(
        "mma.sync.aligned.m16n8k16.row.col.f32.bf16.bf16.f32 "
        "{%0,%1,%2,%3}, {%4,%5,%6,%7}, {%8,%9}, {%0,%1,%2,%3};"
        : "+f"(c[0]), "+f"(c[1]), "+f"(c[2]), "+f"(c[3])
        : "r"(a[0]), "r"(a[1]), "r"(a[2]), "r"(a[3]), "r"(b0), "r"(b1));
}
#define CP_ASYNC16(dst, src) \
    asm volatile("cp.async.cg.shared.global [%0], [%1], 16;" \
                 :: "r"(dst), "l"(src))
#define CP_COMMIT() asm volatile("cp.async.commit_group;" ::: "memory")
#define CP_WAIT0()  asm volatile("cp.async.wait_group 0;" ::: "memory")

#define SWZ(off) ((off) ^ (((off) >> 3) & 0x70))

// ---------------------------------------------------------------------------
__global__ void zerok(float4* __restrict__ p, long n4)
{
    long stride = (long)gridDim.x * blockDim.x;
    for (long i = blockIdx.x * (long)blockDim.x + threadIdx.x; i < n4; i += stride)
        p[i] = make_float4(0.f, 0.f, 0.f, 0.f);
}

// ---------------------------------------------------------------------------
// Prepack B: Wk[kh,kw,Cx,256] + Uk[kh,kw,64,256] -> per-(nblock,kchunk) 16KB
// SW128-swizzled bf16 tiles: 128 N-rows x 64 cols (j<48 valid, j>=48 zero).
// j-blocks: [0,16)=bh, [16,32)=bh, [32,48)=bl   (matches A: ah, al, ah)
// ---------------------------------------------------------------------------
__global__ void prepack_b(const float* __restrict__ Wk, const float* __restrict__ Uk,
                          __nv_bfloat16* __restrict__ Bp,
                          int KH, int Cx, int Ctot, int nchunks)
{
    long idx = blockIdx.x * 256L + threadIdx.x;
    long total = 2L * nchunks * 8192;
    if (idx >= total) return;
    int j = (int)(idx & 63);
    long r = idx >> 6;
    int nrow = (int)(r & 127);
    r >>= 7;
    int kc = (int)(r % nchunks);
    int nb = (int)(r / nchunks);
    __nv_bfloat16 bv = __float2bfloat16(0.f);
    if (j < 48) {
        int part = j >> 4;
        int k = kc * 16 + (j & 15);
        int pos = k / Ctot, c = k % Ctot;
        int n = nb * 128 + nrow;
        float w = (c < Cx) ? Wk[((long)pos * Cx + c) * NCH + n]
                           : Uk[((long)pos * FF + (c - Cx)) * NCH + n];
        __nv_bfloat16 bh = __float2bfloat16(w);
        bv = (part < 2) ? bh : __float2bfloat16(w - __bfloat162float(bh));
    }
    long blk = idx >> 13;                       // / 8192
    int inb = (int)((idx & 8191) * 2);          // byte offset in tile
    int sw = SWZ(inb);
    Bp[blk * 8192 + (sw >> 1)] = bv;
}

// ---------------------------------------------------------------------------
// Transpose x [b,t,pix,32] (NHWC) -> xp [b,t,32,PLANE] planar+halo
// ---------------------------------------------------------------------------
__global__ void transpose_x(const float* __restrict__ x, float* __restrict__ xp)
{
    long idx = blockIdx.x * (long)blockDim.x + threadIdx.x;
    if (idx >= (long)BB * TT * 32 * HWP) return;
    int pix = idx & 4095;
    long rest = idx >> 12;
    int ch = (int)(rest & 31);
    long bt = rest >> 5;
    float v = x[(bt * HWP + pix) * 32 + ch];
    int y = pix >> 6, xx = pix & 63;
    xp[(bt * 32 + ch) * PLANE + (y + 2) * HR + xx + 2] = v;
}

// ---------------------------------------------------------------------------
// Tensor-core implicit-GEMM conv via mma.sync (bf16x3 split for fp32 accuracy).
// CTA: 128m x 128n, 8 warps x (32m x 64n). K chunks of 16 fp32 -> 48 bf16.
// A staged to smem [128m][64k bf16] SW128; B tiles pre-swizzled in gmem,
// copied with cp.async. Double-buffered, one __syncthreads per chunk.
// ---------------------------------------------------------------------------
template<int KH, int Cx, int Ctot, int NCHUNKS>
__global__ void __launch_bounds__(256, 2)
conv_mma(const float* __restrict__ xsrc, int t,
         const float* __restrict__ hprev,
         const __nv_bfloat16* __restrict__ Bpack,
         float* __restrict__ z)
{
    extern __shared__ char smem[];
    const unsigned sb = smem_u32(smem);
    const int tid = threadIdx.x;
    const int lane = tid & 31, wid = tid >> 5;
    const int n_blk = blockIdx.x;          // 0..1
    const int m0 = blockIdx.y * 128;
    const int b = m0 >> 12;
    const int y0 = (m0 & 4095) >> 6;
    constexpr int pad = KH >> 1;
    constexpr int HOFF = 2 - pad;

    // smem: A[2] at 0/16384, B[2] at 32768/49152
    const unsigned sA0 = sb, sB0 = sb + 32768;

    // producer geometry
    const int pix = tid & 127;
    const int g = tid >> 7;
    const int prow = (y0 + (pix >> 6)) * HR + (pix & 63);

    // consumer geometry: warp (mw, nw) tile
    const int mw = wid & 3, nw = wid >> 2;
    int offA[2], offB[4];
#pragma unroll
    for (int mf = 0; mf < 2; mf++)
        offA[mf] = (mw * 32 + mf * 16 + (lane & 15)) * 128 + (lane >> 4) * 16;
#pragma unroll
    for (int nf2 = 0; nf2 < 4; nf2++)
        offB[nf2] = (nw * 64 + nf2 * 16 + (lane >> 4) * 8 + (lane & 7)) * 128
                  + ((lane >> 3) & 1) * 16;

    float acc[16][4];
#pragma unroll
    for (int i = 0; i < 16; i++)
#pragma unroll
        for (int j = 0; j < 4; j++) acc[i][j] = 0.f;

    float a[8];

    auto prefA = [&](int kc) {
        int k0 = kc * 16;
        int pos = k0 / Ctot;
        int cb = k0 - pos * Ctot;
        int ky = pos / KH, kx = pos - ky * KH;
        const float* base = (cb < Cx)
            ? xsrc + ((long)(b * TT + t) * Cx + cb) * PLANE
            : hprev + ((long)b * FF + (cb - Cx)) * PLANE;
        const float* src = base + (long)(g * 8) * PLANE
                         + prow + (ky + HOFF) * HR + kx + HOFF;
#pragma unroll
        for (int r = 0; r < 8; r++) a[r] = __ldg(src + (long)r * PLANE);
    };

    auto cpB = [&](int kc, int s) {
        const char* src = (const char*)(Bpack + ((long)n_blk * NCHUNKS + kc) * 8192)
                        + tid * 16;
        unsigned dst = sB0 + s * 16384 + tid * 16;
#pragma unroll
        for (int i = 0; i < 4; i++)
            CP_ASYNC16(dst + i * 4096, src + i * 4096);
    };

    auto stageA = [&](int s) {
        unsigned hw[4], lw[4];
#pragma unroll
        for (int r = 0; r < 4; r++) {
            hw[r] = pack_bf16x2(a[2 * r + 1], a[2 * r]);
            float ah0 = __uint_as_float(hw[r] << 16);
            float ah1 = __uint_as_float(hw[r] & 0xFFFF0000u);
            lw[r] = pack_bf16x2(a[2 * r + 1] - ah1, a[2 * r] - ah0);
        }
        char* Ab = smem + s * 16384;
        int rb = pix * 128 + 16 * g;
        *(uint4*)(Ab + SWZ(rb))      = make_uint4(hw[0], hw[1], hw[2], hw[3]);
        *(uint4*)(Ab + SWZ(rb + 32)) = make_uint4(lw[0], lw[1], lw[2], lw[3]);
        *(uint4*)(Ab + SWZ(rb + 64)) = make_uint4(hw[0], hw[1], hw[2], hw[3]);
    };

    // prologue
    prefA(0);
    cpB(0, 0);
    CP_COMMIT();
    stageA(0);
    CP_WAIT0();
    __syncthreads();

    for (int kt = 0; kt < NCHUNKS; kt++) {
        const int cur = kt & 1;
        const bool more = (kt + 1 < NCHUNKS);
        if (more) {
            prefA(kt + 1);             // LDGs in flight across compute
            cpB(kt + 1, cur ^ 1);
            CP_COMMIT();
        }

        // ---- tensor-core micro-kernel: 3 k16 steps (ah*bh, al*bh, ah*bl) ----
        const unsigned a_base = sA0 + cur * 16384;
        const unsigned b_base = sB0 + cur * 16384;
#pragma unroll
        for (int ks = 0; ks < 3; ks++) {
            unsigned af[2][4];
            ldsm4(af[0], a_base + SWZ(offA[0] + 32 * ks));
            ldsm4(af[1], a_base + SWZ(offA[1] + 32 * ks));
#pragma unroll
            for (int nf2 = 0; nf2 < 4; nf2++) {
                unsigned bf[4];
                ldsm4(bf, b_base + SWZ(offB[nf2] + 32 * ks));
                mma_bf16(acc[nf2 * 2 + 0],     af[0], bf[0], bf[1]);
                mma_bf16(acc[nf2 * 2 + 1],     af[0], bf[2], bf[3]);
                mma_bf16(acc[8 + nf2 * 2 + 0], af[1], bf[0], bf[1]);
                mma_bf16(acc[8 + nf2 * 2 + 1], af[1], bf[2], bf[3]);
            }
        }

        if (more) {
            stageA(cur ^ 1);
            CP_WAIT0();
        }
        __syncthreads();
    }

    // ---- epilogue: c frag m16n8 -> z ----
#pragma unroll
    for (int mf = 0; mf < 2; mf++) {
        int m = m0 + mw * 32 + mf * 16 + (lane >> 2);
        float* zr = z + (long)m * NCH + n_blk * 128 + nw * 64 + (lane & 3) * 2;
#pragma unroll
        for (int nf = 0; nf < 8; nf++) {
            float* p = zr + nf * 8;
            *(float2*)p = make_float2(acc[mf * 8 + nf][0], acc[mf * 8 + nf][1]);
            *(float2*)(p + 8 * NCH) = make_float2(acc[mf * 8 + nf][2], acc[mf * 8 + nf][3]);
        }
    }
}

// ---------------------------------------------------------------------------
__device__ __forceinline__ float hsig(float v)
{
    return fminf(fmaxf(0.2f * v + 0.5f, 0.f), 1.f);
}

// Layer-1 gates: z[m][n] -> c, h (planar+halo), relu(h) -> h1 seq (planar+halo)
__global__ void __launch_bounds__(256, 2)
gate1(const float* __restrict__ z, const float* __restrict__ bias,
      float* __restrict__ c, float* __restrict__ h,
      float* __restrict__ h1seq, int t)
{
    __shared__ float zs[256 * 33];
    const int tid = threadIdx.x;
    const int m0 = blockIdx.x * 32;
    const int b = m0 >> 12;
    const int pix0 = m0 & 4095;

    float bvv = bias[tid];
    const float* zrow = z + (long)m0 * NCH + tid;
#pragma unroll 8
    for (int r = 0; r < 32; r++)
        zs[tid * 33 + r] = zrow[(long)r * NCH] + bvv;
    __syncthreads();

    const int lane = tid & 31;
    const int fq = tid >> 5;
    const int pix = pix0 + lane;
    const int y = pix >> 6, xx = pix & 63;
    const long hb = (long)b * FF * PLANE;
    const long sbq = (long)(b * TT + t) * FF * PLANE;
    const int hoffpix = (y + 2) * HR + xx + 2;
#pragma unroll
    for (int ff = 0; ff < 8; ff++) {
        int f = fq * 8 + ff;
        float zi = zs[f * 33 + lane];
        float zf = zs[(64 + f) * 33 + lane];
        float zc = zs[(128 + f) * 33 + lane];
        float zo = zs[(192 + f) * 33 + lane];
        long cidx = ((long)b * FF + f) * HWP + pix;
        float cn = hsig(zf) * c[cidx] + hsig(zi) * tanhf(zc);
        float hn = hsig(zo) * tanhf(cn);
        c[cidx] = cn;
        long ho = (long)f * PLANE + hoffpix;
        h[hb + ho] = hn;
        h1seq[sbq + ho] = fmaxf(hn, 0.f);
    }
}

// Layer-2 gates: also emit NHWC output via a second smem transpose.
__global__ void __launch_bounds__(256, 2)
gate2(const float* __restrict__ z, const float* __restrict__ bias,
      float* __restrict__ c, float* __restrict__ h,
      float* __restrict__ out, int t)
{
    __shared__ float zs[256 * 33];
    __shared__ float hs[64 * 33];
    const int tid = threadIdx.x;
    const int m0 = blockIdx.x * 32;
    const int b = m0 >> 12;
    const int pix0 = m0 & 4095;

    float bvv = bias[tid];
    const float* zrow = z + (long)m0 * NCH + tid;
#pragma unroll 8
    for (int r = 0; r < 32; r++)
        zs[tid * 33 + r] = zrow[(long)r * NCH] + bvv;
    __syncthreads();

    const int lane = tid & 31;
    const int fq = tid >> 5;
    const int pix = pix0 + lane;
    const int y = pix >> 6, xx = pix & 63;
    const long hb = (long)b * FF * PLANE;
    const int hoffpix = (y + 2) * HR + xx + 2;
#pragma unroll
    for (int ff = 0; ff < 8; ff++) {
        int f = fq * 8 + ff;
        float zi = zs[f * 33 + lane];
        float zf = zs[(64 + f) * 33 + lane];
        float zc = zs[(128 + f) * 33 + lane];
        float zo = zs[(192 + f) * 33 + lane];
        long cidx = ((long)b * FF + f) * HWP + pix;
        float cn = hsig(zf) * c[cidx] + hsig(zi) * tanhf(zc);
        float hn = hsig(zo) * tanhf(cn);
        c[cidx] = cn;
        h[hb + (long)f * PLANE + hoffpix] = hn;
        hs[f * 33 + lane] = fmaxf(hn, 0.f);
    }
    __syncthreads();

    float* ob = out + ((long)(b * TT + t) * HWP + pix0) * FF;
#pragma unroll
    for (int r = 0; r < 8; r++) {
        int e = r * 256 + tid;
        int f = e & 63;
        int mo = e >> 6;
        ob[(long)mo * FF + f] = hs[f * 33 + mo];
    }
}

// ---------------------------------------------------------------------------
extern "C" void kernel_launch(void* const* d_in, const int* in_sizes, int n_in,
                              void* d_out, int out_size)
{
    const float* x   = (const float*)d_in[0];
    const float* Wk1 = (const float*)d_in[1];
    const float* Uk1 = (const float*)d_in[2];
    const float* b1  = (const float*)d_in[3];
    const float* Wk2 = (const float*)d_in[4];
    const float* Uk2 = (const float*)d_in[5];
    const float* b2  = (const float*)d_in[6];
    float* out = (float*)d_out;

    float *z, *xp, *h1, *h, *c;
    __nv_bfloat16 *B1, *B2;
    cudaGetSymbolAddress((void**)&z,  g_z);
    cudaGetSymbolAddress((void**)&xp, g_xp);
    cudaGetSymbolAddress((void**)&h1, g_h1);
    cudaGetSymbolAddress((void**)&h,  g_h);
    cudaGetSymbolAddress((void**)&c,  g_c);
    cudaGetSymbolAddress((void**)&B1, g_B1);
    cudaGetSymbolAddress((void**)&B2, g_B2);

    static int smem_set = 0;
    if (!smem_set) {
        cudaFuncSetAttribute(conv_mma<5, 32, 96, NCH1>,
                             cudaFuncAttributeMaxDynamicSharedMemorySize, SM_TOTAL);
        cudaFuncSetAttribute(conv_mma<3, 64, 128, NCH2>,
                             cudaFuncAttributeMaxDynamicSharedMemorySize, SM_TOTAL);
        smem_set = 1;
    }

    // One-time per launch: zero halo buffers, prepack weights, transpose x
    zerok<<<1024, 256>>>((float4*)xp, (long)BB * TT * 32 * PLANE / 4);
    zerok<<<1024, 256>>>((float4*)h1, (long)BB * TT * FF * PLANE / 4);
    {
        long tot1 = 2L * NCH1 * 8192, tot2 = 2L * NCH2 * 8192;
        prepack_b<<<(int)((tot1 + 255) / 256), 256>>>(Wk1, Uk1, B1, 5, 32, 96, NCH1);
        prepack_b<<<(int)((tot2 + 255) / 256), 256>>>(Wk2, Uk2, B2, 3, 64, 128, NCH2);
        long totx = (long)BB * TT * 32 * HWP;
        transpose_x<<<(int)((totx + 255) / 256), 256>>>(x, xp);
    }

    const dim3 grid(2, M_TOTAL / 128);   // (n-blocks, m-blocks) = (2, 256)
    const int gateBlocks = M_TOTAL / 32; // 1024

    // ---- Layer 1: 5x5, Cx=32, Ctot=96, K=2400 ----
    zerok<<<1024, 256>>>((float4*)h, (long)BB * FF * PLANE / 4);
    zerok<<<1024, 256>>>((float4*)c, (long)BB * FF * HWP / 4);
    for (int t = 0; t < TT; t++) {
        conv_mma<5, 32, 96, NCH1><<<grid, 256, SM_TOTAL>>>(xp, t, h, B1, z);
        gate1<<<gateBlocks, 256>>>(z, b1, c, h, h1, t);
    }

    // ---- Layer 2: 3x3, Cx=64, Ctot=128, K=1152 ----
    zerok<<<1024, 256>>>((float4*)h, (long)BB * FF * PLANE / 4);
    zerok<<<1024, 256>>>((float4*)c, (long)BB * FF * HWP / 4);
    for (int t = 0; t < TT; t++) {
        conv_mma<3, 64, 128, NCH2><<<grid, 256, SM_TOTAL>>>(h1, t, h, B2, z);
        gate2<<<gateBlocks, 256>>>(z, b2, c, h, out, t);
    }
}

// round 8
// speedup vs baseline: 4.8877x; 1.4894x over previous
#include <cuda_runtime.h>
#include <cuda_fp16.h>
#include <math.h>

// Problem constants
#define BB 8
#define TT 10
#define HH 64
#define WW 64
#define HWP 4096           // H*W
#define FF 64
#define NCH 256            // 4*F
#define M_TOTAL (BB*HWP)   // 32768
#define M_BIG   (BB*TT*HWP) // 327680

// Planar halo layout: 2-pixel border on each side
#define HR 68
#define PLANE (HR*HR)      // 4624 floats per channel plane

// K chunk = 32 fp32 channels -> 64 fp16 cols in A (ah|al), 32 fp16 in B (bh)
#define NC1X 25            // layer1 x-part:  K=800  (25 taps x 32ch) /32
#define NC1H 50            // layer1 h-part:  K=1600 (25 x 64) /32
#define NC2  18            // layer2 x/h:     K=576  (9 x 64) /32

// SMEM: A[2][16KB] @0, B[2][8KB] @32768
#define SM_TOTAL 49152

// Scratch (static device globals; no allocation allowed)
__device__ float g_zx[(long)M_BIG * NCH];           // precomputed W*x part (336MB)
__device__ float g_z[(long)M_TOTAL * NCH];          // per-step gate pre-activations
__device__ float g_xp[(long)BB * TT * 32 * PLANE];  // x planar+halo
__device__ float g_h1[(long)BB * TT * FF * PLANE];  // relu(h) seq layer1, planar+halo
__device__ float g_h[(long)BB * FF * PLANE];        // hidden state, planar+halo
__device__ float g_c[(long)BB * FF * HWP];          // cell state, planar
__device__ __half g_B1x[(long)2 * NC1X * 4096];     // prepacked B tiles (bh only)
__device__ __half g_B1h[(long)2 * NC1H * 4096];
__device__ __half g_B2x[(long)2 * NC2 * 4096];
__device__ __half g_B2h[(long)2 * NC2 * 4096];

// ---------------------------------------------------------------------------
// Helpers (sm_80-baseline PTX only — harness targets family-generic sm_103)
// ---------------------------------------------------------------------------
__device__ __forceinline__ unsigned smem_u32(const void* p) {
    unsigned r;
    asm("{ .reg .u64 t; cvta.to.shared.u64 t, %1; cvt.u32.u64 %0, t; }"
        : "=r"(r) : "l"(p));
    return r;
}
__device__ __forceinline__ unsigned pack_f16x2(float hi, float lo) {
    unsigned r;
    asm("cvt.rn.f16x2.f32 %0, %1, %2;" : "=r"(r) : "f"(hi), "f"(lo));
    return r;
}
__device__ __forceinline__ void ldsm4(unsigned* r, unsigned addr) {
    asm volatile("ldmatrix.sync.aligned.m8n8.x4.shared.b16 {%0,%1,%2,%3}, [%4];"
                 : "=r"(r[0]), "=r"(r[1]), "=r"(r[2]), "=r"(r[3]) : "r"(addr));
}
__device__ __forceinline__ void mma_f16(float* c, const unsigned* a,
                                        unsigned b0, unsigned b1) {
    asm volatile(
        "mma.sync.aligned.m16n8k16.row.col.f32.f16.f16.f32 "
        "{%0,%1,%2,%3}, {%4,%5,%6,%7}, {%8,%9}, {%0,%1,%2,%3};"
        : "+f"(c[0]), "+f"(c[1]), "+f"(c[2]), "+f"(c[3])
        : "r"(a[0]), "r"(a[1]), "r"(a[2]), "r"(a[3]), "r"(b0), "r"(b1));
}
#define CP_ASYNC16(dst, src) \
    asm volatile("cp.async.cg.shared.global [%0], [%1], 16;" \
                 :: "r"(dst), "l"(src))
#define CP_COMMIT() asm volatile("cp.async.commit_group;" ::: "memory")
#define CP_WAIT0()  asm volatile("cp.async.wait_group 0;" ::: "memory")

#define SWZ(off)   ((off) ^ (((off) >> 3) & 0x70))   // 128B-row swizzle (A)
#define SWZ64(off) ((off) ^ (((off) >> 3) & 0x30))   // 64B-row swizzle (B)

// ---------------------------------------------------------------------------
__global__ void zerok(float4* __restrict__ p, long n4)
{
    long stride = (long)gridDim.x * blockDim.x;
    for (long i = blockIdx.x * (long)blockDim.x + threadIdx.x; i < n4; i += stride)
        p[i] = make_float4(0.f, 0.f, 0.f, 0.f);
}

// ---------------------------------------------------------------------------
// Prepack B: W [kh,kw,Cin,256] -> per-(nblock,kchunk) 8KB tile:
// 128 N-rows x 32 fp16 (= 32 orig K), 64B rows, SWZ64-swizzled.
// ---------------------------------------------------------------------------
__global__ void prepack_b(const float* __restrict__ W, __half* __restrict__ Bp,
                          int Cin, int nchunks)
{
    long idx = blockIdx.x * 256L + threadIdx.x;
    long total = 2L * nchunks * 4096;
    if (idx >= total) return;
    int j = (int)(idx & 31);            // orig k within chunk
    long r = idx >> 5;
    int nrow = (int)(r & 127);
    r >>= 7;
    int kc = (int)(r % nchunks);
    int nb = (int)(r / nchunks);
    int k = kc * 32 + j;
    int pos = k / Cin, c = k % Cin;
    int n = nb * 128 + nrow;
    float w = W[((long)pos * Cin + c) * NCH + n];
    int inb = nrow * 64 + j * 2;
    int sw = SWZ64(inb);
    long tile = idx >> 12;              // nb*nchunks + kc
    Bp[tile * 4096 + (sw >> 1)] = __float2half_rn(w);
}

// ---------------------------------------------------------------------------
// Transpose x [b,t,pix,32] (NHWC) -> xp [b,t,32,PLANE] planar+halo
// ---------------------------------------------------------------------------
__global__ void transpose_x(const float* __restrict__ x, float* __restrict__ xp)
{
    long idx = blockIdx.x * (long)blockDim.x + threadIdx.x;
    if (idx >= (long)BB * TT * 32 * HWP) return;
    int pix = idx & 4095;
    long rest = idx >> 12;
    int ch = (int)(rest & 31);
    long bt = rest >> 5;
    float v = x[(bt * HWP + pix) * 32 + ch];
    int y = pix >> 6, xx = pix & 63;
    xp[(bt * 32 + ch) * PLANE + (y + 2) * HR + xx + 2] = v;
}

// ---------------------------------------------------------------------------
// Tensor-core implicit-GEMM conv via mma.sync, fp16x2 split:
//   a = ah + al (fp16); a*b ≈ ah*bh + al*bh  (drops a*bl, ~2^-12 rel)
// CTA: 128m x 128n, 8 warps x (32m x 64n). K chunks of 32 fp32.
// A smem [128m][64 fp16] (ah|al) SW128; B smem [128n][32 fp16] (bh) SWZ64,
// pre-swizzled in gmem, cp.async. Double-buffered.
// ADD=true: out = acc + zadd tile (recurrent step); else out = acc (big GEMM).
// Source plane: src + (bt*CIN + ch)*PLANE, bt = m>>12.
// ---------------------------------------------------------------------------
template<int CIN, int KH, int NCHUNKS, bool ADD>
__global__ void __launch_bounds__(256, 2)
conv_mma(const float* __restrict__ src,
         const __half* __restrict__ Bpack,
         float* __restrict__ zout,
         const float* __restrict__ zadd, int t)
{
    extern __shared__ char smem[];
    const unsigned sb = smem_u32(smem);
    const int tid = threadIdx.x;
    const int lane = tid & 31, wid = tid >> 5;
    const int n_blk = blockIdx.x;          // 0..1
    const int m0 = blockIdx.y * 128;
    const int bt = m0 >> 12;
    const int y0 = (m0 & 4095) >> 6;
    constexpr int pad = KH >> 1;
    constexpr int HOFF = 2 - pad;

    const unsigned sA0 = sb, sB0 = sb + 32768;

    // producer geometry
    const int pix = tid & 127;
    const int g = tid >> 7;                // 0/1: channels g*16..g*16+15 of chunk
    const int prow = (y0 + (pix >> 6)) * HR + (pix & 63);

    // consumer geometry: warp (mw, nw) tile = 32m x 64n
    const int mw = wid & 3, nw = wid >> 2;
    int offA[2], offB[4];
#pragma unroll
    for (int mf = 0; mf < 2; mf++)
        offA[mf] = (mw * 32 + mf * 16 + (lane & 15)) * 128 + (lane >> 4) * 16;
#pragma unroll
    for (int nf2 = 0; nf2 < 4; nf2++)
        offB[nf2] = (nw * 64 + nf2 * 16 + (lane >> 4) * 8 + (lane & 7)) * 64
                  + ((lane >> 3) & 1) * 16;

    float acc[16][4];
#pragma unroll
    for (int i = 0; i < 16; i++)
#pragma unroll
        for (int j = 0; j < 4; j++) acc[i][j] = 0.f;

    float a[16];

    auto prefA = [&](int kc) {
        int k0 = kc * 32;
        int pos = k0 / CIN;
        int cb = k0 - pos * CIN;
        int ky = pos / KH, kx = pos - ky * KH;
        const float* s = src + ((long)bt * CIN + cb + g * 16) * PLANE
                       + prow + (ky + HOFF) * HR + kx + HOFF;
#pragma unroll
        for (int r = 0; r < 16; r++) a[r] = __ldg(s + (long)r * PLANE);
    };

    auto cpB = [&](int kc, int s) {
        const char* gsrc = (const char*)(Bpack + ((long)n_blk * NCHUNKS + kc) * 4096)
                         + tid * 16;
        unsigned dst = sB0 + s * 8192 + tid * 16;
        CP_ASYNC16(dst, gsrc);
        CP_ASYNC16(dst + 4096, gsrc + 4096);
    };

    auto stageA = [&](int s) {
        unsigned hw[8], lw[8];
#pragma unroll
        for (int j = 0; j < 8; j++) {
            float f0 = a[2 * j], f1 = a[2 * j + 1];
            __half h0 = __float2half_rn(f0);
            __half h1 = __float2half_rn(f1);
            hw[j] = pack_f16x2(f1, f0);        // rn pack == (h1,h0)
            lw[j] = pack_f16x2(f1 - __half2float(h1), f0 - __half2float(h0));
        }
        char* Ab = smem + s * 16384;
        int rb = pix * 128 + g * 32;           // ah region cols [0,64)B
#pragma unroll
        for (int q = 0; q < 2; q++) {
            *(uint4*)(Ab + SWZ(rb + q * 16)) =
                make_uint4(hw[q * 4], hw[q * 4 + 1], hw[q * 4 + 2], hw[q * 4 + 3]);
            *(uint4*)(Ab + SWZ(rb + 64 + q * 16)) =
                make_uint4(lw[q * 4], lw[q * 4 + 1], lw[q * 4 + 2], lw[q * 4 + 3]);
        }
    };

    // prologue
    prefA(0);
    cpB(0, 0);
    CP_COMMIT();
    stageA(0);
    CP_WAIT0();
    __syncthreads();

    for (int kt = 0; kt < NCHUNKS; kt++) {
        const int cur = kt & 1;
        const bool more = (kt + 1 < NCHUNKS);
        if (more) {
            prefA(kt + 1);
            cpB(kt + 1, cur ^ 1);
            CP_COMMIT();
        }

        const unsigned a_base = sA0 + cur * 16384;
        const unsigned b_base = sB0 + cur * 8192;
#pragma unroll
        for (int ks = 0; ks < 2; ks++) {       // two k16 halves of the 32-chunk
            unsigned bf[4][4];
#pragma unroll
            for (int nf2 = 0; nf2 < 4; nf2++)
                ldsm4(bf[nf2], b_base + SWZ64(offB[nf2] + ks * 32));
#pragma unroll
            for (int term = 0; term < 2; term++) {   // ah*bh, al*bh (B reused)
                unsigned af[2][4];
                ldsm4(af[0], a_base + SWZ(offA[0] + term * 64 + ks * 32));
                ldsm4(af[1], a_base + SWZ(offA[1] + term * 64 + ks * 32));
#pragma unroll
                for (int nf2 = 0; nf2 < 4; nf2++) {
                    mma_f16(acc[nf2 * 2 + 0],     af[0], bf[nf2][0], bf[nf2][1]);
                    mma_f16(acc[nf2 * 2 + 1],     af[0], bf[nf2][2], bf[nf2][3]);
                    mma_f16(acc[8 + nf2 * 2 + 0], af[1], bf[nf2][0], bf[nf2][1]);
                    mma_f16(acc[8 + nf2 * 2 + 1], af[1], bf[nf2][2], bf[nf2][3]);
                }
            }
        }

        if (more) {
            stageA(cur ^ 1);
            CP_WAIT0();
        }
        __syncthreads();
    }

    // ---- epilogue ----
    const float* za = nullptr;
    if (ADD)
        za = zadd + (((long)bt * TT + t) * HWP + (m0 & 4095)) * NCH;
#pragma unroll
    for (int mf = 0; mf < 2; mf++) {
        int ml = mw * 32 + mf * 16 + (lane >> 2);
        long coff = (long)n_blk * 128 + nw * 64 + (lane & 3) * 2;
        float* zr = zout + (long)(m0 + ml) * NCH + coff;
        const float* zar = ADD ? (za + (long)ml * NCH + coff) : nullptr;
#pragma unroll
        for (int nf = 0; nf < 8; nf++) {
            float2 v0 = make_float2(acc[mf * 8 + nf][0], acc[mf * 8 + nf][1]);
            float2 v1 = make_float2(acc[mf * 8 + nf][2], acc[mf * 8 + nf][3]);
            if (ADD) {
                float2 w0 = *(const float2*)(zar + nf * 8);
                float2 w1 = *(const float2*)(zar + nf * 8 + 8 * NCH);
                v0.x += w0.x; v0.y += w0.y; v1.x += w1.x; v1.y += w1.y;
            }
            *(float2*)(zr + nf * 8) = v0;
            *(float2*)(zr + nf * 8 + 8 * NCH) = v1;
        }
    }
}

// ---------------------------------------------------------------------------
__device__ __forceinline__ float hsig(float v)
{
    return fminf(fmaxf(0.2f * v + 0.5f, 0.f), 1.f);
}

// Layer-1 gates: z[m][n] -> c, h (planar+halo), relu(h) -> h1 seq (planar+halo)
__global__ void __launch_bounds__(256, 2)
gate1(const float* __restrict__ z, const float* __restrict__ bias,
      float* __restrict__ c, float* __restrict__ h,
      float* __restrict__ h1seq, int t)
{
    __shared__ float zs[256 * 33];
    const int tid = threadIdx.x;
    const int m0 = blockIdx.x * 32;
    const int b = m0 >> 12;
    const int pix0 = m0 & 4095;

    float bvv = bias[tid];
    const float* zrow = z + (long)m0 * NCH + tid;
#pragma unroll 8
    for (int r = 0; r < 32; r++)
        zs[tid * 33 + r] = zrow[(long)r * NCH] + bvv;
    __syncthreads();

    const int lane = tid & 31;
    const int fq = tid >> 5;
    const int pix = pix0 + lane;
    const int y = pix >> 6, xx = pix & 63;
    const long hb = (long)b * FF * PLANE;
    const long sbq = (long)(b * TT + t) * FF * PLANE;
    const int hoffpix = (y + 2) * HR + xx + 2;
#pragma unroll
    for (int ff = 0; ff < 8; ff++) {
        int f = fq * 8 + ff;
        float zi = zs[f * 33 + lane];
        float zf = zs[(64 + f) * 33 + lane];
        float zc = zs[(128 + f) * 33 + lane];
        float zo = zs[(192 + f) * 33 + lane];
        long cidx = ((long)b * FF + f) * HWP + pix;
        float cn = hsig(zf) * c[cidx] + hsig(zi) * tanhf(zc);
        float hn = hsig(zo) * tanhf(cn);
        c[cidx] = cn;
        long ho = (long)f * PLANE + hoffpix;
        h[hb + ho] = hn;
        h1seq[sbq + ho] = fmaxf(hn, 0.f);
    }
}

// Layer-2 gates: also emit NHWC output via a second smem transpose.
__global__ void __launch_bounds__(256, 2)
gate2(const float* __restrict__ z, const float* __restrict__ bias,
      float* __restrict__ c, float* __restrict__ h,
      float* __restrict__ out, int t)
{
    __shared__ float zs[256 * 33];
    __shared__ float hs[64 * 33];
    const int tid = threadIdx.x;
    const int m0 = blockIdx.x * 32;
    const int b = m0 >> 12;
    const int pix0 = m0 & 4095;

    float bvv = bias[tid];
    const float* zrow = z + (long)m0 * NCH + tid;
#pragma unroll 8
    for (int r = 0; r < 32; r++)
        zs[tid * 33 + r] = zrow[(long)r * NCH] + bvv;
    __syncthreads();

    const int lane = tid & 31;
    const int fq = tid >> 5;
    const int pix = pix0 + lane;
    const int y = pix >> 6, xx = pix & 63;
    const long hb = (long)b * FF * PLANE;
    const int hoffpix = (y + 2) * HR + xx + 2;
#pragma unroll
    for (int ff = 0; ff < 8; ff++) {
        int f = fq * 8 + ff;
        float zi = zs[f * 33 + lane];
        float zf = zs[(64 + f) * 33 + lane];
        float zc = zs[(128 + f) * 33 + lane];
        float zo = zs[(192 + f) * 33 + lane];
        long cidx = ((long)b * FF + f) * HWP + pix;
        float cn = hsig(zf) * c[cidx] + hsig(zi) * tanhf(zc);
        float hn = hsig(zo) * tanhf(cn);
        c[cidx] = cn;
        h[hb + (long)f * PLANE + hoffpix] = hn;
        hs[f * 33 + lane] = fmaxf(hn, 0.f);
    }
    __syncthreads();

    float* ob = out + ((long)(b * TT + t) * HWP + pix0) * FF;
#pragma unroll
    for (int r = 0; r < 8; r++) {
        int e = r * 256 + tid;
        int f = e & 63;
        int mo = e >> 6;
        ob[(long)mo * FF + f] = hs[f * 33 + mo];
    }
}

// ---------------------------------------------------------------------------
extern "C" void kernel_launch(void* const* d_in, const int* in_sizes, int n_in,
                              void* d_out, int out_size)
{
    const float* x   = (const float*)d_in[0];
    const float* Wk1 = (const float*)d_in[1];
    const float* Uk1 = (const float*)d_in[2];
    const float* b1  = (const float*)d_in[3];
    const float* Wk2 = (const float*)d_in[4];
    const float* Uk2 = (const float*)d_in[5];
    const float* b2  = (const float*)d_in[6];
    float* out = (float*)d_out;

    float *zx, *z, *xp, *h1, *h, *c;
    __half *B1x, *B1h, *B2x, *B2h;
    cudaGetSymbolAddress((void**)&zx, g_zx);
    cudaGetSymbolAddress((void**)&z,  g_z);
    cudaGetSymbolAddress((void**)&xp, g_xp);
    cudaGetSymbolAddress((void**)&h1, g_h1);
    cudaGetSymbolAddress((void**)&h,  g_h);
    cudaGetSymbolAddress((void**)&c,  g_c);
    cudaGetSymbolAddress((void**)&B1x, g_B1x);
    cudaGetSymbolAddress((void**)&B1h, g_B1h);
    cudaGetSymbolAddress((void**)&B2x, g_B2x);
    cudaGetSymbolAddress((void**)&B2h, g_B2h);

    static int smem_set = 0;
    if (!smem_set) {
        cudaFuncSetAttribute(conv_mma<32, 5, NC1X, false>,
                             cudaFuncAttributeMaxDynamicSharedMemorySize, SM_TOTAL);
        cudaFuncSetAttribute(conv_mma<64, 5, NC1H, true>,
                             cudaFuncAttributeMaxDynamicSharedMemorySize, SM_TOTAL);
        cudaFuncSetAttribute(conv_mma<64, 3, NC2, false>,
                             cudaFuncAttributeMaxDynamicSharedMemorySize, SM_TOTAL);
        cudaFuncSetAttribute(conv_mma<64, 3, NC2, true>,
                             cudaFuncAttributeMaxDynamicSharedMemorySize, SM_TOTAL);
        smem_set = 1;
    }

    // Setup: zero halo buffers, prepack weights, transpose x
    zerok<<<1024, 256>>>((float4*)xp, (long)BB * TT * 32 * PLANE / 4);
    zerok<<<1024, 256>>>((float4*)h1, (long)BB * TT * FF * PLANE / 4);
    prepack_b<<<(int)((2L * NC1X * 4096 + 255) / 256), 256>>>(Wk1, B1x, 32, NC1X);
    prepack_b<<<(int)((2L * NC1H * 4096 + 255) / 256), 256>>>(Uk1, B1h, 64, NC1H);
    prepack_b<<<(int)((2L * NC2 * 4096 + 255) / 256), 256>>>(Wk2, B2x, 64, NC2);
    prepack_b<<<(int)((2L * NC2 * 4096 + 255) / 256), 256>>>(Uk2, B2h, 64, NC2);
    {
        long totx = (long)BB * TT * 32 * HWP;
        transpose_x<<<(int)((totx + 255) / 256), 256>>>(x, xp);
    }

    const dim3 gridBig(2, M_BIG / 128);   // (2, 2560)
    const dim3 gridRec(2, M_TOTAL / 128); // (2, 256)
    const int gateBlocks = M_TOTAL / 32;  // 1024

    // ---- Layer 1 ----
    // zx = W1 * x for all timesteps (one big GEMM, K=800)
    conv_mma<32, 5, NC1X, false><<<gridBig, 256, SM_TOTAL>>>(xp, B1x, zx, nullptr, 0);
    zerok<<<1024, 256>>>((float4*)h, (long)BB * FF * PLANE / 4);
    zerok<<<1024, 256>>>((float4*)c, (long)BB * FF * HWP / 4);
    for (int t = 0; t < TT; t++) {
        conv_mma<64, 5, NC1H, true><<<gridRec, 256, SM_TOTAL>>>(h, B1h, z, zx, t);
        gate1<<<gateBlocks, 256>>>(z, b1, c, h, h1, t);
    }

    // ---- Layer 2 ----
    // zx = W2 * h1 for all timesteps (one big GEMM, K=576)
    conv_mma<64, 3, NC2, false><<<gridBig, 256, SM_TOTAL>>>(h1, B2x, zx, nullptr, 0);
    zerok<<<1024, 256>>>((float4*)h, (long)BB * FF * PLANE / 4);
    zerok<<<1024, 256>>>((float4*)c, (long)BB * FF * HWP / 4);
    for (int t = 0; t < TT; t++) {
        conv_mma<64, 3, NC2, true><<<gridRec, 256, SM_TOTAL>>>(h, B2h, z, zx, t);
        gate2<<<gateBlocks, 256>>>(z, b2, c, h, out, t);
    }
}

// round 9
// speedup vs baseline: 5.0853x; 1.0404x over previous
#include <cuda_runtime.h>
#include <cuda_fp16.h>
#include <math.h>

// Problem constants
#define BB 8
#define TT 10
#define HH 64
#define WW 64
#define HWP 4096           // H*W
#define FF 64
#define NCH 256            // 4*F
#define M_TOTAL (BB*HWP)   // 32768
#define M_BIG   (BB*TT*HWP) // 327680

// Planar halo layout: 2-pixel border on each side
#define HR 68
#define PLANE (HR*HR)      // 4624 per channel plane

// K chunk = 32 fp32 channels -> 64 fp16 cols in A (ah|al), 32 fp16 in B (bh)
#define NC1X 25            // layer1 x-part:  K=800  (25 taps x 32ch) /32
#define NC1H 50            // layer1 h-part:  K=1600 (25 x 64) /32
#define NC2  18            // layer2 x/h:     K=576  (9 x 64) /32

// SMEM: A[2][16KB] @0, B[2][8KB] @32768
#define SM_TOTAL 49152

// Scratch (static device globals; no allocation allowed)
// Activation planes are packed u32 = fp16(hi) | fp16(lo)<<16  (hi+lo == fp32 value)
__device__ float    g_zx[(long)M_BIG * NCH];           // precomputed W*x part
__device__ float    g_z[(long)M_TOTAL * NCH];          // per-step gate pre-activations
__device__ unsigned g_xp[(long)BB * TT * 32 * PLANE];  // x planar+halo, packed hi/lo
__device__ unsigned g_h1[(long)BB * TT * FF * PLANE];  // relu(h) seq layer1, packed
__device__ unsigned g_h[(long)BB * FF * PLANE];        // hidden state, packed
__device__ float    g_c[(long)BB * FF * HWP];          // cell state, planar fp32
__device__ __half g_B1x[(long)2 * NC1X * 4096];        // prepacked B tiles (bh only)
__device__ __half g_B1h[(long)2 * NC1H * 4096];
__device__ __half g_B2x[(long)2 * NC2 * 4096];
__device__ __half g_B2h[(long)2 * NC2 * 4096];

// ---------------------------------------------------------------------------
// Helpers (sm_80-baseline PTX only — harness targets family-generic sm_103)
// ---------------------------------------------------------------------------
__device__ __forceinline__ unsigned smem_u32(const void* p) {
    unsigned r;
    asm("{ .reg .u64 t; cvta.to.shared.u64 t, %1; cvt.u32.u64 %0, t; }"
        : "=r"(r) : "l"(p));
    return r;
}
__device__ __forceinline__ unsigned pack_hl(float f) {
    __half h = __float2half_rn(f);
    float r = f - __half2float(h);
    return (unsigned)__half_as_ushort(h)
         | ((unsigned)__half_as_ushort(__float2half_rn(r)) << 16);
}
__device__ __forceinline__ void ldsm4(unsigned* r, unsigned addr) {
    asm volatile("ldmatrix.sync.aligned.m8n8.x4.shared.b16 {%0,%1,%2,%3}, [%4];"
                 : "=r"(r[0]), "=r"(r[1]), "=r"(r[2]), "=r"(r[3]) : "r"(addr));
}
__device__ __forceinline__ void mma_f16(float* c, const unsigned* a,
                                        unsigned b0, unsigned b1) {
    asm volatile(
        "mma.sync.aligned.m16n8k16.row.col.f32.f16.f16.f32 "
        "{%0,%1,%2,%3}, {%4,%5,%6,%7}, {%8,%9}, {%0,%1,%2,%3};"
        : "+f"(c[0]), "+f"(c[1]), "+f"(c[2]), "+f"(c[3])
        : "r"(a[0]), "r"(a[1]), "r"(a[2]), "r"(a[3]), "r"(b0), "r"(b1));
}
#define CP_ASYNC16(dst, src) \
    asm volatile("cp.async.cg.shared.global [%0], [%1], 16;" \
                 :: "r"(dst), "l"(src))
#define CP_COMMIT() asm volatile("cp.async.commit_group;" ::: "memory")
#define CP_WAIT0()  asm volatile("cp.async.wait_group 0;" ::: "memory")

#define SWZ(off)   ((off) ^ (((off) >> 3) & 0x70))   // 128B-row swizzle (A)
#define SWZ64(off) ((off) ^ (((off) >> 3) & 0x30))   // 64B-row swizzle (B)

// ---------------------------------------------------------------------------
__global__ void zerok(float4* __restrict__ p, long n4)
{
    long stride = (long)gridDim.x * blockDim.x;
    for (long i = blockIdx.x * (long)blockDim.x + threadIdx.x; i < n4; i += stride)
        p[i] = make_float4(0.f, 0.f, 0.f, 0.f);
}

// ---------------------------------------------------------------------------
// Prepack all 4 weight sets in ONE kernel (keeps launch order stable for ncu).
// W [kh,kw,Cin,256] -> per-(nblock,kchunk) 8KB tile:
// 128 N-rows x 32 fp16 (= 32 orig K), 64B rows, SWZ64-swizzled.
// ---------------------------------------------------------------------------
__device__ __forceinline__ void prepack_one(long idx, const float* __restrict__ W,
                                            __half* __restrict__ Bp, int Cin, int nch)
{
    int j = (int)(idx & 31);
    long r = idx >> 5;
    int nrow = (int)(r & 127);
    r >>= 7;
    int kc = (int)(r % nch);
    int nb = (int)(r / nch);
    int k = kc * 32 + j;
    int pos = k / Cin, c = k % Cin;
    int n = nb * 128 + nrow;
    float w = W[((long)pos * Cin + c) * NCH + n];
    int inb = nrow * 64 + j * 2;
    int sw = SWZ64(inb);
    long tile = idx >> 12;
    Bp[tile * 4096 + (sw >> 1)] = __float2half_rn(w);
}

__global__ void prepack_all(const float* __restrict__ W1, const float* __restrict__ U1,
                            const float* __restrict__ W2, const float* __restrict__ U2,
                            __half* __restrict__ B1x, __half* __restrict__ B1h,
                            __half* __restrict__ B2x, __half* __restrict__ B2h)
{
    long idx = blockIdx.x * 256L + threadIdx.x;
    if (idx < 204800)       prepack_one(idx,          W1, B1x, 32, NC1X);
    else if (idx < 614400)  prepack_one(idx - 204800, U1, B1h, 64, NC1H);
    else if (idx < 761856)  prepack_one(idx - 614400, W2, B2x, 64, NC2);
    else if (idx < 909312)  prepack_one(idx - 761856, U2, B2h, 64, NC2);
}

// ---------------------------------------------------------------------------
// Transpose x [b,t,pix,32] (NHWC fp32) -> xp [b,t,32,PLANE] packed hi/lo planes
// ---------------------------------------------------------------------------
__global__ void transpose_x(const float* __restrict__ x, unsigned* __restrict__ xp)
{
    long idx = blockIdx.x * (long)blockDim.x + threadIdx.x;
    if (idx >= (long)BB * TT * 32 * HWP) return;
    int pix = idx & 4095;
    long rest = idx >> 12;
    int ch = (int)(rest & 31);
    long bt = rest >> 5;
    float v = x[(bt * HWP + pix) * 32 + ch];
    int y = pix >> 6, xx = pix & 63;
    xp[(bt * 32 + ch) * PLANE + (y + 2) * HR + xx + 2] = pack_hl(v);
}

// ---------------------------------------------------------------------------
// Tensor-core implicit-GEMM conv via mma.sync, fp16x2 split:
//   a = ah + al (fp16); a*b ≈ ah*bh + al*bh  (drops a*bl, ~2^-12 rel)
// Activations arrive PRE-SPLIT as packed u32 planes -> producer is LDG + PRMT.
// CTA: 128m x 128n, 8 warps x (32m x 64n). K chunks of 32 fp32.
// ADD=true: out = acc + zadd tile (recurrent step); else out = acc (big GEMM).
// ---------------------------------------------------------------------------
template<int CIN, int KH, int NCHUNKS, bool ADD>
__global__ void __launch_bounds__(256, 2)
conv_mma(const unsigned* __restrict__ src,
         const __half* __restrict__ Bpack,
         float* __restrict__ zout,
         const float* __restrict__ zadd, int t)
{
    extern __shared__ char smem[];
    const unsigned sb = smem_u32(smem);
    const int tid = threadIdx.x;
    const int lane = tid & 31, wid = tid >> 5;
    const int n_blk = blockIdx.x;          // 0..1
    const int m0 = blockIdx.y * 128;
    const int bt = m0 >> 12;
    const int y0 = (m0 & 4095) >> 6;
    constexpr int pad = KH >> 1;
    constexpr int HOFF = 2 - pad;

    const unsigned sA0 = sb, sB0 = sb + 32768;

    // producer geometry
    const int pix = tid & 127;
    const int g = tid >> 7;                // 0/1: channels g*16..g*16+15 of chunk
    const int prow = (y0 + (pix >> 6)) * HR + (pix & 63);

    // consumer geometry: warp (mw, nw) tile = 32m x 64n
    const int mw = wid & 3, nw = wid >> 2;
    int offA[2], offB[4];
#pragma unroll
    for (int mf = 0; mf < 2; mf++)
        offA[mf] = (mw * 32 + mf * 16 + (lane & 15)) * 128 + (lane >> 4) * 16;
#pragma unroll
    for (int nf2 = 0; nf2 < 4; nf2++)
        offB[nf2] = (nw * 64 + nf2 * 16 + (lane >> 4) * 8 + (lane & 7)) * 64
                  + ((lane >> 3) & 1) * 16;

    float acc[16][4];
#pragma unroll
    for (int i = 0; i < 16; i++)
#pragma unroll
        for (int j = 0; j < 4; j++) acc[i][j] = 0.f;

    unsigned a[16];

    auto prefA = [&](int kc) {
        int k0 = kc * 32;
        int pos = k0 / CIN;
        int cb = k0 - pos * CIN;
        int ky = pos / KH, kx = pos - ky * KH;
        const unsigned* s = src + ((long)bt * CIN + cb + g * 16) * PLANE
                          + prow + (ky + HOFF) * HR + kx + HOFF;
#pragma unroll
        for (int r = 0; r < 16; r++) a[r] = __ldg(s + (long)r * PLANE);
    };

    auto cpB = [&](int kc, int s) {
        const char* gsrc = (const char*)(Bpack + ((long)n_blk * NCHUNKS + kc) * 4096)
                         + tid * 16;
        unsigned dst = sB0 + s * 8192 + tid * 16;
        CP_ASYNC16(dst, gsrc);
        CP_ASYNC16(dst + 4096, gsrc + 4096);
    };

    auto stageA = [&](int s) {
        unsigned hw[8], lw[8];
#pragma unroll
        for (int j = 0; j < 8; j++) {
            hw[j] = __byte_perm(a[2 * j], a[2 * j + 1], 0x5410);  // (ah0, ah1)
            lw[j] = __byte_perm(a[2 * j], a[2 * j + 1], 0x7632);  // (al0, al1)
        }
        char* Ab = smem + s * 16384;
        int rb = pix * 128 + g * 32;           // ah region cols; al at +64B
#pragma unroll
        for (int q = 0; q < 2; q++) {
            *(uint4*)(Ab + SWZ(rb + q * 16)) =
                make_uint4(hw[q * 4], hw[q * 4 + 1], hw[q * 4 + 2], hw[q * 4 + 3]);
            *(uint4*)(Ab + SWZ(rb + 64 + q * 16)) =
                make_uint4(lw[q * 4], lw[q * 4 + 1], lw[q * 4 + 2], lw[q * 4 + 3]);
        }
    };

    // prologue
    prefA(0);
    cpB(0, 0);
    CP_COMMIT();
    stageA(0);
    CP_WAIT0();
    __syncthreads();

    for (int kt = 0; kt < NCHUNKS; kt++) {
        const int cur = kt & 1;
        const bool more = (kt + 1 < NCHUNKS);
        if (more) {
            prefA(kt + 1);
            cpB(kt + 1, cur ^ 1);
            CP_COMMIT();
        }

        const unsigned a_base = sA0 + cur * 16384;
        const unsigned b_base = sB0 + cur * 8192;
#pragma unroll
        for (int ks = 0; ks < 2; ks++) {       // two k16 halves of the 32-chunk
            unsigned bf[4][4];
#pragma unroll
            for (int nf2 = 0; nf2 < 4; nf2++)
                ldsm4(bf[nf2], b_base + SWZ64(offB[nf2] + ks * 32));
#pragma unroll
            for (int term = 0; term < 2; term++) {   // ah*bh, al*bh (B reused)
                unsigned af[2][4];
                ldsm4(af[0], a_base + SWZ(offA[0] + term * 64 + ks * 32));
                ldsm4(af[1], a_base + SWZ(offA[1] + term * 64 + ks * 32));
#pragma unroll
                for (int nf2 = 0; nf2 < 4; nf2++) {
                    mma_f16(acc[nf2 * 2 + 0],     af[0], bf[nf2][0], bf[nf2][1]);
                    mma_f16(acc[nf2 * 2 + 1],     af[0], bf[nf2][2], bf[nf2][3]);
                    mma_f16(acc[8 + nf2 * 2 + 0], af[1], bf[nf2][0], bf[nf2][1]);
                    mma_f16(acc[8 + nf2 * 2 + 1], af[1], bf[nf2][2], bf[nf2][3]);
                }
            }
        }

        if (more) {
            stageA(cur ^ 1);
            CP_WAIT0();
        }
        __syncthreads();
    }

    // ---- epilogue ----
    const float* za = nullptr;
    if (ADD)
        za = zadd + (((long)bt * TT + t) * HWP + (m0 & 4095)) * NCH;
#pragma unroll
    for (int mf = 0; mf < 2; mf++) {
        int ml = mw * 32 + mf * 16 + (lane >> 2);
        long coff = (long)n_blk * 128 + nw * 64 + (lane & 3) * 2;
        float* zr = zout + (long)(m0 + ml) * NCH + coff;
        const float* zar = ADD ? (za + (long)ml * NCH + coff) : nullptr;
#pragma unroll
        for (int nf = 0; nf < 8; nf++) {
            float2 v0 = make_float2(acc[mf * 8 + nf][0], acc[mf * 8 + nf][1]);
            float2 v1 = make_float2(acc[mf * 8 + nf][2], acc[mf * 8 + nf][3]);
            if (ADD) {
                float2 w0 = *(const float2*)(zar + nf * 8);
                float2 w1 = *(const float2*)(zar + nf * 8 + 8 * NCH);
                v0.x += w0.x; v0.y += w0.y; v1.x += w1.x; v1.y += w1.y;
            }
            *(float2*)(zr + nf * 8) = v0;
            *(float2*)(zr + nf * 8 + 8 * NCH) = v1;
        }
    }
}

// ---------------------------------------------------------------------------
__device__ __forceinline__ float hsig(float v)
{
    return fminf(fmaxf(0.2f * v + 0.5f, 0.f), 1.f);
}

// Layer-1 gates: z[m][n] -> c (fp32), h packed, relu(h) -> h1 seq packed
__global__ void __launch_bounds__(256, 2)
gate1(const float* __restrict__ z, const float* __restrict__ bias,
      float* __restrict__ c, unsigned* __restrict__ h,
      unsigned* __restrict__ h1seq, int t)
{
    __shared__ float zs[256 * 33];
    const int tid = threadIdx.x;
    const int m0 = blockIdx.x * 32;
    const int b = m0 >> 12;
    const int pix0 = m0 & 4095;

    float bvv = bias[tid];
    const float* zrow = z + (long)m0 * NCH + tid;
#pragma unroll 8
    for (int r = 0; r < 32; r++)
        zs[tid * 33 + r] = zrow[(long)r * NCH] + bvv;
    __syncthreads();

    const int lane = tid & 31;
    const int fq = tid >> 5;
    const int pix = pix0 + lane;
    const int y = pix >> 6, xx = pix & 63;
    const long hb = (long)b * FF * PLANE;
    const long sbq = (long)(b * TT + t) * FF * PLANE;
    const int hoffpix = (y + 2) * HR + xx + 2;
#pragma unroll
    for (int ff = 0; ff < 8; ff++) {
        int f = fq * 8 + ff;
        float zi = zs[f * 33 + lane];
        float zf = zs[(64 + f) * 33 + lane];
        float zc = zs[(128 + f) * 33 + lane];
        float zo = zs[(192 + f) * 33 + lane];
        long cidx = ((long)b * FF + f) * HWP + pix;
        float cn = hsig(zf) * c[cidx] + hsig(zi) * tanhf(zc);
        float hn = hsig(zo) * tanhf(cn);
        c[cidx] = cn;
        long ho = (long)f * PLANE + hoffpix;
        h[hb + ho] = pack_hl(hn);
        h1seq[sbq + ho] = pack_hl(fmaxf(hn, 0.f));
    }
}

// Layer-2 gates: h packed; NHWC fp32 output via smem transpose.
__global__ void __launch_bounds__(256, 2)
gate2(const float* __restrict__ z, const float* __restrict__ bias,
      float* __restrict__ c, unsigned* __restrict__ h,
      float* __restrict__ out, int t)
{
    __shared__ float zs[256 * 33];
    __shared__ float hs[64 * 33];
    const int tid = threadIdx.x;
    const int m0 = blockIdx.x * 32;
    const int b = m0 >> 12;
    const int pix0 = m0 & 4095;

    float bvv = bias[tid];
    const float* zrow = z + (long)m0 * NCH + tid;
#pragma unroll 8
    for (int r = 0; r < 32; r++)
        zs[tid * 33 + r] = zrow[(long)r * NCH] + bvv;
    __syncthreads();

    const int lane = tid & 31;
    const int fq = tid >> 5;
    const int pix = pix0 + lane;
    const int y = pix >> 6, xx = pix & 63;
    const long hb = (long)b * FF * PLANE;
    const int hoffpix = (y + 2) * HR + xx + 2;
#pragma unroll
    for (int ff = 0; ff < 8; ff++) {
        int f = fq * 8 + ff;
        float zi = zs[f * 33 + lane];
        float zf = zs[(64 + f) * 33 + lane];
        float zc = zs[(128 + f) * 33 + lane];
        float zo = zs[(192 + f) * 33 + lane];
        long cidx = ((long)b * FF + f) * HWP + pix;
        float cn = hsig(zf) * c[cidx] + hsig(zi) * tanhf(zc);
        float hn = hsig(zo) * tanhf(cn);
        c[cidx] = cn;
        h[hb + (long)f * PLANE + hoffpix] = pack_hl(hn);
        hs[f * 33 + lane] = fmaxf(hn, 0.f);
    }
    __syncthreads();

    float* ob = out + ((long)(b * TT + t) * HWP + pix0) * FF;
#pragma unroll
    for (int r = 0; r < 8; r++) {
        int e = r * 256 + tid;
        int f = e & 63;
        int mo = e >> 6;
        ob[(long)mo * FF + f] = hs[f * 33 + mo];
    }
}

// ---------------------------------------------------------------------------
extern "C" void kernel_launch(void* const* d_in, const int* in_sizes, int n_in,
                              void* d_out, int out_size)
{
    const float* x   = (const float*)d_in[0];
    const float* Wk1 = (const float*)d_in[1];
    const float* Uk1 = (const float*)d_in[2];
    const float* b1  = (const float*)d_in[3];
    const float* Wk2 = (const float*)d_in[4];
    const float* Uk2 = (const float*)d_in[5];
    const float* b2  = (const float*)d_in[6];
    float* out = (float*)d_out;

    float *zx, *z, *c;
    unsigned *xp, *h1, *h;
    __half *B1x, *B1h, *B2x, *B2h;
    cudaGetSymbolAddress((void**)&zx, g_zx);
    cudaGetSymbolAddress((void**)&z,  g_z);
    cudaGetSymbolAddress((void**)&xp, g_xp);
    cudaGetSymbolAddress((void**)&h1, g_h1);
    cudaGetSymbolAddress((void**)&h,  g_h);
    cudaGetSymbolAddress((void**)&c,  g_c);
    cudaGetSymbolAddress((void**)&B1x, g_B1x);
    cudaGetSymbolAddress((void**)&B1h, g_B1h);
    cudaGetSymbolAddress((void**)&B2x, g_B2x);
    cudaGetSymbolAddress((void**)&B2h, g_B2h);

    static int smem_set = 0;
    if (!smem_set) {
        cudaFuncSetAttribute(conv_mma<32, 5, NC1X, false>,
                             cudaFuncAttributeMaxDynamicSharedMemorySize, SM_TOTAL);
        cudaFuncSetAttribute(conv_mma<64, 5, NC1H, true>,
                             cudaFuncAttributeMaxDynamicSharedMemorySize, SM_TOTAL);
        cudaFuncSetAttribute(conv_mma<64, 3, NC2, false>,
                             cudaFuncAttributeMaxDynamicSharedMemorySize, SM_TOTAL);
        cudaFuncSetAttribute(conv_mma<64, 3, NC2, true>,
                             cudaFuncAttributeMaxDynamicSharedMemorySize, SM_TOTAL);
        smem_set = 1;
    }

    const dim3 gridBig(2, M_BIG / 128);   // (2, 2560)
    const dim3 gridRec(2, M_TOTAL / 128); // (2, 256)
    const int gateBlocks = M_TOTAL / 32;  // 1024

    // Launch order is deliberate: index 3 = layer-1 big GEMM (ncu captures it).
    // [0] prepack all weights
    prepack_all<<<(909312 + 255) / 256, 256>>>(Wk1, Uk1, Wk2, Uk2, B1x, B1h, B2x, B2h);
    // [1] zero xp (halo), [2] transpose x into packed planes
    zerok<<<1024, 256>>>((float4*)xp, (long)BB * TT * 32 * PLANE / 4);
    {
        long totx = (long)BB * TT * 32 * HWP;
        transpose_x<<<(int)((totx + 255) / 256), 256>>>(x, xp);
    }
    // [3] zx = W1 * x for all timesteps (one big GEMM, K=800)  <-- PROFILED
    conv_mma<32, 5, NC1X, false><<<gridBig, 256, SM_TOTAL>>>(xp, B1x, zx, nullptr, 0);
    // [4..6] zero h, c, h1 halos
    zerok<<<1024, 256>>>((float4*)h, (long)BB * FF * PLANE / 4);
    zerok<<<1024, 256>>>((float4*)c, (long)BB * FF * HWP / 4);
    zerok<<<1024, 256>>>((float4*)h1, (long)BB * TT * FF * PLANE / 4);

    // ---- Layer 1 recurrence ----
    for (int t = 0; t < TT; t++) {
        conv_mma<64, 5, NC1H, true><<<gridRec, 256, SM_TOTAL>>>(h, B1h, z, zx, t);
        gate1<<<gateBlocks, 256>>>(z, b1, c, h, h1, t);
    }

    // ---- Layer 2 ----
    // zx = W2 * h1 for all timesteps (one big GEMM, K=576)
    conv_mma<64, 3, NC2, false><<<gridBig, 256, SM_TOTAL>>>(h1, B2x, zx, nullptr, 0);
    zerok<<<1024, 256>>>((float4*)h, (long)BB * FF * PLANE / 4);
    zerok<<<1024, 256>>>((float4*)c, (long)BB * FF * HWP / 4);
    for (int t = 0; t < TT; t++) {
        conv_mma<64, 3, NC2, true><<<gridRec, 256, SM_TOTAL>>>(h, B2h, z, zx, t);
        gate2<<<gateBlocks, 256>>>(z, b2, c, h, out, t);
    }
}